// round 3
// baseline (speedup 1.0000x reference)
#include <cuda_runtime.h>
#include <math.h>

// Problem constants (fixed shapes from reference)
#define U_LEN   2048
#define B_SZ    16
#define D_CH    512
#define R_LEN   512
#define T_TOT   2560            // R + U
#define NROWS   40960           // T_TOT * B_SZ
#define CS      30              // cache size = KERNEL_SIZE-1
#define KS      31
#define CHUNK   32
#define RCL     8
#define NCHUNK  64              // R / RCL

#define UTT_OUT_ELEMS ((size_t)U_LEN * B_SZ * D_CH)   // 16777216
#define RC_OUT_ELEMS  ((size_t)R_LEN * B_SZ * D_CH)   // 4194304
#define CACHE_OUT_OFF (UTT_OUT_ELEMS + RC_OUT_ELEMS)  // 20971520

// Scratch (static device allocations; allowed per harness rules)
__device__ float g_glu[(size_t)NROWS * D_CH];   // GLU output, layout [t_glob*16+b][d]
__device__ float g_z[(size_t)NROWS * D_CH];     // depthwise+swish output, same layout

static __device__ __forceinline__ float sigmoidf_(float x) {
    return 1.0f / (1.0f + __expf(-x));
}

// ---------------------------------------------------------------------------
// Kernel 1: pointwise conv1 (D -> 2D) fused with GLU.
//   X row n = t*16+b:  t<512 -> right_context, else utterance (both (T,B,D)).
//   glu[n][d] = (b1[d] + X.W1a) * sigmoid(b1[512+d] + X.W1g)
// Tiling: 128 rows x 64 d-cols; B smem holds 64 'a' cols + 64 'g' cols.
// 256 threads, each computes 8 rows x 4 cols of a AND g.
// ---------------------------------------------------------------------------
__global__ __launch_bounds__(256) void k_gemm1_glu(
    const float* __restrict__ utt, const float* __restrict__ rc,
    const float* __restrict__ w1, const float* __restrict__ b1)
{
    __shared__ float As[8][128];
    __shared__ float Bs[8][128];   // cols [0,64): a-weights, [64,128): g-weights

    const int tid  = threadIdx.x;
    const int row0 = blockIdx.y * 128;
    const int c0   = blockIdx.x * 64;

    const int ldr = tid >> 1;          // 0..127
    const int ldc = (tid & 1) * 4;     // 0 or 4

    const int n = row0 + ldr;
    const float* aptr = (n < R_LEN * B_SZ)
        ? (rc  + (size_t)n * D_CH + ldc)
        : (utt + (size_t)(n - R_LEN * B_SZ) * D_CH + ldc);

    const int wrow = (ldr < 64) ? (c0 + ldr) : (D_CH + c0 + (ldr - 64));
    const float* wptr = w1 + (size_t)wrow * D_CH + ldc;

    const int tx = tid & 15;
    const int ty = tid >> 4;

    float acc_a[8][4];
    float acc_g[8][4];
    #pragma unroll
    for (int i = 0; i < 8; i++) {
        #pragma unroll
        for (int j = 0; j < 4; j++) { acc_a[i][j] = 0.f; acc_g[i][j] = 0.f; }
    }

    for (int k0 = 0; k0 < D_CH; k0 += 8) {
        float4 av = *(const float4*)(aptr + k0);
        float4 bv = *(const float4*)(wptr + k0);
        As[ldc + 0][ldr] = av.x; As[ldc + 1][ldr] = av.y;
        As[ldc + 2][ldr] = av.z; As[ldc + 3][ldr] = av.w;
        Bs[ldc + 0][ldr] = bv.x; Bs[ldc + 1][ldr] = bv.y;
        Bs[ldc + 2][ldr] = bv.z; Bs[ldc + 3][ldr] = bv.w;
        __syncthreads();

        #pragma unroll
        for (int kk = 0; kk < 8; kk++) {
            float4 a0 = *(const float4*)&As[kk][ty * 8];
            float4 a1 = *(const float4*)&As[kk][ty * 8 + 4];
            float4 ba = *(const float4*)&Bs[kk][tx * 4];
            float4 bg = *(const float4*)&Bs[kk][64 + tx * 4];
            float ar[8]  = {a0.x, a0.y, a0.z, a0.w, a1.x, a1.y, a1.z, a1.w};
            float bar[4] = {ba.x, ba.y, ba.z, ba.w};
            float bgr[4] = {bg.x, bg.y, bg.z, bg.w};
            #pragma unroll
            for (int i = 0; i < 8; i++) {
                #pragma unroll
                for (int j = 0; j < 4; j++) {
                    acc_a[i][j] += ar[i] * bar[j];
                    acc_g[i][j] += ar[i] * bgr[j];
                }
            }
        }
        __syncthreads();
    }

    #pragma unroll
    for (int j = 0; j < 4; j++) {
        const int d = c0 + tx * 4 + j;
        const float biasa = b1[d];
        const float biasg = b1[D_CH + d];
        #pragma unroll
        for (int i = 0; i < 8; i++) {
            const int row = row0 + ty * 8 + i;
            const float a = acc_a[i][j] + biasa;
            const float g = acc_g[i][j] + biasg;
            g_glu[(size_t)row * D_CH + d] = a * sigmoidf_(g);
        }
    }
}

// ---------------------------------------------------------------------------
// Kernel 2a: depthwise conv on the utterance part + swish -> g_z rows t>=512.
// Thread: one channel d, 8 consecutive output times. pad position pp:
//   pp < 30 -> cache[b][d][pp], else glu at t_glob = 512 + pp - 30.
// ---------------------------------------------------------------------------
__global__ __launch_bounds__(256) void k_dw_utt(
    const float* __restrict__ cache,
    const float* __restrict__ wd, const float* __restrict__ bd)
{
    const int d  = blockIdx.x * 256 + threadIdx.x;   // 0..511
    const int t0 = blockIdx.y * 8;                   // output time tile
    const int b  = blockIdx.z;

    float w[KS];
    #pragma unroll
    for (int k = 0; k < KS; k++) w[k] = wd[(size_t)d * KS + k];

    float s[38];
    #pragma unroll
    for (int p = 0; p < 38; p++) {
        const int pp = t0 + p;   // position in pad_utt (length 30+U)
        if (pp < CS)
            s[p] = cache[((size_t)b * D_CH + d) * CS + pp];
        else
            s[p] = g_glu[((size_t)(R_LEN + pp - CS) * B_SZ + b) * D_CH + d];
    }

    const float bias = bd[d];
    #pragma unroll
    for (int j = 0; j < 8; j++) {
        float acc = bias;
        #pragma unroll
        for (int k = 0; k < KS; k++) acc += w[k] * s[j + k];
        const float r = acc * sigmoidf_(acc - 1.0f);
        const int tg = R_LEN + t0 + j;
        g_z[((size_t)tg * B_SZ + b) * D_CH + d] = r;
    }
}

// ---------------------------------------------------------------------------
// Kernel 2b: depthwise conv on the right-context chunks + swish -> g_z rows t<512.
// Chunk c: seq = [glu_utt times (c+1)*32-30 .. +29]  ++  [glu_rc times c*8 .. c*8+7]
// (start index min() is a no-op since (c+1)*32 <= U for all c)
// ---------------------------------------------------------------------------
__global__ __launch_bounds__(256) void k_dw_rc(
    const float* __restrict__ wd, const float* __restrict__ bd)
{
    const int d = blockIdx.x * 256 + threadIdx.x;
    const int c = blockIdx.y;   // 0..63
    const int b = blockIdx.z;   // 0..15

    float w[KS];
    #pragma unroll
    for (int k = 0; k < KS; k++) w[k] = wd[(size_t)d * KS + k];

    float s[38];
    const int base_t = R_LEN + (c + 1) * CHUNK - CS;  // glu t_glob of pad start
    #pragma unroll
    for (int p = 0; p < 30; p++)
        s[p] = g_glu[((size_t)(base_t + p) * B_SZ + b) * D_CH + d];
    #pragma unroll
    for (int p = 0; p < 8; p++)
        s[30 + p] = g_glu[((size_t)(c * RCL + p) * B_SZ + b) * D_CH + d];

    const float bias = bd[d];
    #pragma unroll
    for (int j = 0; j < RCL; j++) {
        float acc = bias;
        #pragma unroll
        for (int k = 0; k < KS; k++) acc += w[k] * s[j + k];
        const float r = acc * sigmoidf_(acc - 1.0f);
        const int tg = c * RCL + j;
        g_z[((size_t)tg * B_SZ + b) * D_CH + d] = r;
    }
}

// ---------------------------------------------------------------------------
// Kernel 3: new_cache = glu utt times [U-30, U) -> out[CACHE_OUT_OFF + (b*D+d)*30+i]
// ---------------------------------------------------------------------------
__global__ void k_cache(float* __restrict__ out)
{
    const int e = blockIdx.x * 256 + threadIdx.x;
    if (e >= B_SZ * D_CH * CS) return;
    const int i   = e % CS;
    const int bd_ = e / CS;         // b*512 + d
    const int d   = bd_ & (D_CH - 1);
    const int b   = bd_ >> 9;
    const int tg  = T_TOT - CS + i; // 2530 + i
    out[CACHE_OUT_OFF + e] = g_glu[((size_t)tg * B_SZ + b) * D_CH + d];
}

// ---------------------------------------------------------------------------
// Kernel 4: pointwise conv2 (D -> D) + bias, routed into final output regions.
//   rows n < 8192 (t<512)  -> rc_final  at out[UTT + n*512 + o]
//   rows n >= 8192         -> utt_final at out[(n-8192)*512 + o]
// Classic 128x128x8 SGEMM, 256 threads, 8x8 per thread.
// ---------------------------------------------------------------------------
__global__ __launch_bounds__(256) void k_gemm2(
    const float* __restrict__ w2, const float* __restrict__ b2,
    float* __restrict__ out)
{
    __shared__ float As[8][128];
    __shared__ float Bs[8][128];

    const int tid  = threadIdx.x;
    const int row0 = blockIdx.y * 128;
    const int o0   = blockIdx.x * 128;

    const int ldr = tid >> 1;
    const int ldc = (tid & 1) * 4;

    const float* aptr = g_z + (size_t)(row0 + ldr) * D_CH + ldc;
    const float* wptr = w2  + (size_t)(o0 + ldr) * D_CH + ldc;

    const int tx = tid & 15;
    const int ty = tid >> 4;

    float acc[8][8];
    #pragma unroll
    for (int i = 0; i < 8; i++)
        #pragma unroll
        for (int j = 0; j < 8; j++) acc[i][j] = 0.f;

    for (int k0 = 0; k0 < D_CH; k0 += 8) {
        float4 av = *(const float4*)(aptr + k0);
        float4 bv = *(const float4*)(wptr + k0);
        As[ldc + 0][ldr] = av.x; As[ldc + 1][ldr] = av.y;
        As[ldc + 2][ldr] = av.z; As[ldc + 3][ldr] = av.w;
        Bs[ldc + 0][ldr] = bv.x; Bs[ldc + 1][ldr] = bv.y;
        Bs[ldc + 2][ldr] = bv.z; Bs[ldc + 3][ldr] = bv.w;
        __syncthreads();

        #pragma unroll
        for (int kk = 0; kk < 8; kk++) {
            float4 a0 = *(const float4*)&As[kk][ty * 8];
            float4 a1 = *(const float4*)&As[kk][ty * 8 + 4];
            float4 b0 = *(const float4*)&Bs[kk][tx * 8];
            float4 b1v = *(const float4*)&Bs[kk][tx * 8 + 4];
            float ar[8] = {a0.x, a0.y, a0.z, a0.w, a1.x, a1.y, a1.z, a1.w};
            float br[8] = {b0.x, b0.y, b0.z, b0.w, b1v.x, b1v.y, b1v.z, b1v.w};
            #pragma unroll
            for (int i = 0; i < 8; i++)
                #pragma unroll
                for (int j = 0; j < 8; j++)
                    acc[i][j] += ar[i] * br[j];
        }
        __syncthreads();
    }

    #pragma unroll
    for (int j = 0; j < 8; j++) {
        const int o = o0 + tx * 8 + j;
        const float bias = b2[o];
        #pragma unroll
        for (int i = 0; i < 8; i++) {
            const int n = row0 + ty * 8 + i;
            const float y = acc[i][j] + bias;
            if (n >= R_LEN * B_SZ)
                out[(size_t)(n - R_LEN * B_SZ) * D_CH + o] = y;        // utt_final
            else
                out[UTT_OUT_ELEMS + (size_t)n * D_CH + o] = y;         // rc_final
        }
    }
}

// ---------------------------------------------------------------------------
extern "C" void kernel_launch(void* const* d_in, const int* in_sizes, int n_in,
                              void* d_out, int out_size)
{
    const float* utt   = (const float*)d_in[0];
    const float* rc    = (const float*)d_in[1];
    const float* cache = (const float*)d_in[2];
    const float* w1    = (const float*)d_in[3];
    const float* b1    = (const float*)d_in[4];
    const float* wd    = (const float*)d_in[5];
    const float* bd    = (const float*)d_in[6];
    const float* w2    = (const float*)d_in[7];
    const float* b2    = (const float*)d_in[8];
    float* out = (float*)d_out;

    // 1) pointwise conv1 + GLU  -> g_glu
    k_gemm1_glu<<<dim3(D_CH / 64, NROWS / 128), 256>>>(utt, rc, w1, b1);

    // 2) depthwise + swish -> g_z  (utt part, rc chunks), cache slice
    k_dw_utt<<<dim3(2, U_LEN / 8, B_SZ), 256>>>(cache, wd, bd);
    k_dw_rc <<<dim3(2, NCHUNK, B_SZ), 256>>>(wd, bd);
    k_cache<<<(B_SZ * D_CH * CS + 255) / 256, 256>>>(out);

    // 3) pointwise conv2 + bias -> final outputs
    k_gemm2<<<dim3(D_CH / 128, NROWS / 128), 256>>>(w2, b2, out);
}

// round 8
// speedup vs baseline: 1.9199x; 1.9199x over previous
#include <cuda_runtime.h>
#include <math.h>

// Problem constants (fixed shapes from reference)
#define U_LEN   2048
#define B_SZ    16
#define D_CH    512
#define R_LEN   512
#define T_TOT   2560            // R + U
#define NROWS   40960           // T_TOT * B_SZ
#define CS      30              // cache size = KERNEL_SIZE-1
#define KS      31
#define CHUNK   32
#define RCL     8
#define NCHUNK  64              // R / RCL
#define RB      (R_LEN * B_SZ)  // 8192 rows of right-context

#define UTT_OUT_ELEMS ((size_t)U_LEN * B_SZ * D_CH)   // 16777216
#define RC_OUT_ELEMS  ((size_t)R_LEN * B_SZ * D_CH)   // 4194304
#define CACHE_OUT_OFF (UTT_OUT_ELEMS + RC_OUT_ELEMS)  // 20971520

#define LDA 36   // smem row stride (floats); 36 % 32 == 4 -> conflict-free frag loads

// Scratch (static device arrays; allowed)
__device__ float g_glu[(size_t)NROWS * D_CH];   // GLU output, [t_glob*16+b][d]
__device__ float g_z[(size_t)NROWS * D_CH];     // depthwise+swish output

static __device__ __forceinline__ float sigmoidf_(float x) {
    return 1.0f / (1.0f + __expf(-x));
}
static __device__ __forceinline__ unsigned f2tf(float x) {
    unsigned y; asm("cvt.rna.tf32.f32 %0, %1;" : "=r"(y) : "f"(x)); return y;
}
static __device__ __forceinline__ void mma8(float* c, const unsigned* a, const unsigned* b) {
    asm volatile(
        "mma.sync.aligned.m16n8k8.row.col.f32.tf32.tf32.f32 "
        "{%0,%1,%2,%3},{%4,%5,%6,%7},{%8,%9},{%0,%1,%2,%3};"
        : "+f"(c[0]), "+f"(c[1]), "+f"(c[2]), "+f"(c[3])
        : "r"(a[0]), "r"(a[1]), "r"(a[2]), "r"(a[3]), "r"(b[0]), "r"(b[1]));
}

// ---------------------------------------------------------------------------
// Kernel 1: pointwise conv1 (D -> 2D) + GLU, tf32 tensor-core GEMM.
// Block: 128 rows x 64 d-cols of GLU output. B-tile = 128 W1 rows:
//   smem rows [0,64)  -> 'a' rows  c0+j
//   smem rows [64,128)-> 'g' rows  512+c0+(j-64)
// 8 warps (4 m x 2 n). Each warp: 32 m x 32 d; n-frags 0..3 = a, 4..7 = g
// (same d!), so GLU fuses in registers.
// ---------------------------------------------------------------------------
__global__ __launch_bounds__(256) void k_gemm1_glu(
    const float* __restrict__ utt, const float* __restrict__ rc,
    const float* __restrict__ w1, const float* __restrict__ b1)
{
    __shared__ unsigned As[128 * LDA];
    __shared__ unsigned Bs[128 * LDA];

    const int tid  = threadIdx.x;
    const int lane = tid & 31, warp = tid >> 5;
    const int wm   = warp >> 1;      // 0..3
    const int wn   = warp & 1;       // 0..1
    const int row0 = blockIdx.y * 128;
    const int c0   = blockIdx.x * 64;

    float acc[2][8][4];
    #pragma unroll
    for (int mi = 0; mi < 2; mi++)
        #pragma unroll
        for (int f = 0; f < 8; f++)
            #pragma unroll
            for (int q = 0; q < 4; q++) acc[mi][f][q] = 0.f;

    for (int kt = 0; kt < 16; kt++) {
        const int kbase = kt * 32;
        #pragma unroll
        for (int i = 0; i < 4; i++) {          // A: 128 rows x 32 k
            const int f = i * 256 + tid;
            const int r = f >> 3, kq = f & 7;
            const int n = row0 + r;
            const float* src = (n < RB) ? (rc + (size_t)n * D_CH)
                                        : (utt + (size_t)(n - RB) * D_CH);
            float4 v = *(const float4*)(src + kbase + kq * 4);
            unsigned* p = &As[r * LDA + kq * 4];
            p[0] = f2tf(v.x); p[1] = f2tf(v.y); p[2] = f2tf(v.z); p[3] = f2tf(v.w);
        }
        #pragma unroll
        for (int i = 0; i < 4; i++) {          // B: 128 W1 rows x 32 k
            const int f = i * 256 + tid;
            const int j = f >> 3, kq = f & 7;
            const int wr = (j < 64) ? (c0 + j) : (D_CH + c0 + (j - 64));
            float4 v = *(const float4*)(w1 + (size_t)wr * D_CH + kbase + kq * 4);
            unsigned* p = &Bs[j * LDA + kq * 4];
            p[0] = f2tf(v.x); p[1] = f2tf(v.y); p[2] = f2tf(v.z); p[3] = f2tf(v.w);
        }
        __syncthreads();

        #pragma unroll
        for (int ksub = 0; ksub < 4; ksub++) {
            const int k0 = ksub * 8 + (lane & 3);
            unsigned a[2][4];
            #pragma unroll
            for (int mi = 0; mi < 2; mi++) {
                const int base = (wm * 32 + mi * 16 + (lane >> 2)) * LDA + k0;
                a[mi][0] = As[base];
                a[mi][1] = As[base + 8 * LDA];
                a[mi][2] = As[base + 4];
                a[mi][3] = As[base + 8 * LDA + 4];
            }
            unsigned bf[8][2];
            #pragma unroll
            for (int f = 0; f < 8; f++) {
                const int jn = ((f < 4) ? (wn * 32 + f * 8)
                                        : (64 + wn * 32 + (f - 4) * 8)) + (lane >> 2);
                bf[f][0] = Bs[jn * LDA + k0];
                bf[f][1] = Bs[jn * LDA + k0 + 4];
            }
            #pragma unroll
            for (int mi = 0; mi < 2; mi++)
                #pragma unroll
                for (int f = 0; f < 8; f++)
                    mma8(acc[mi][f], a[mi], bf[f]);
        }
        __syncthreads();
    }

    // Epilogue: GLU in registers (a-frag f pairs with g-frag f+4, same d)
    #pragma unroll
    for (int mi = 0; mi < 2; mi++) {
        #pragma unroll
        for (int rh = 0; rh < 2; rh++) {
            const int row = row0 + wm * 32 + mi * 16 + (lane >> 2) + rh * 8;
            #pragma unroll
            for (int f = 0; f < 4; f++) {
                const int d = c0 + wn * 32 + f * 8 + 2 * (lane & 3);
                const float a0 = acc[mi][f][rh * 2 + 0] + b1[d];
                const float a1 = acc[mi][f][rh * 2 + 1] + b1[d + 1];
                const float g0 = acc[mi][f + 4][rh * 2 + 0] + b1[D_CH + d];
                const float g1 = acc[mi][f + 4][rh * 2 + 1] + b1[D_CH + d + 1];
                float2 o;
                o.x = a0 * sigmoidf_(g0);
                o.y = a1 * sigmoidf_(g1);
                *(float2*)&g_glu[(size_t)row * D_CH + d] = o;
            }
        }
    }
}

// ---------------------------------------------------------------------------
// Kernel 2a: depthwise conv (utterance) + swish -> g_z rows t>=512.
// One channel d, 16 consecutive output times per thread.
// ---------------------------------------------------------------------------
__global__ __launch_bounds__(256) void k_dw_utt(
    const float* __restrict__ cache,
    const float* __restrict__ wd, const float* __restrict__ bd)
{
    const int d  = blockIdx.x * 256 + threadIdx.x;   // 0..511
    const int t0 = blockIdx.y * 16;                  // output time tile
    const int b  = blockIdx.z;

    float w[KS];
    #pragma unroll
    for (int k = 0; k < KS; k++) w[k] = wd[(size_t)d * KS + k];

    float s[46];
    #pragma unroll
    for (int p = 0; p < 46; p++) {
        const int pp = t0 + p;   // position in pad_utt (length 30+U)
        if (pp < CS)
            s[p] = cache[((size_t)b * D_CH + d) * CS + pp];
        else
            s[p] = g_glu[((size_t)(R_LEN + pp - CS) * B_SZ + b) * D_CH + d];
    }

    const float bias = bd[d];
    #pragma unroll
    for (int j = 0; j < 16; j++) {
        float acc = bias;
        #pragma unroll
        for (int k = 0; k < KS; k++) acc += w[k] * s[j + k];
        const float r = acc * sigmoidf_(acc - 1.0f);
        const int tg = R_LEN + t0 + j;
        g_z[((size_t)tg * B_SZ + b) * D_CH + d] = r;
    }
}

// ---------------------------------------------------------------------------
// Kernel 2b: depthwise conv (right-context chunks) + swish -> g_z rows t<512.
// ---------------------------------------------------------------------------
__global__ __launch_bounds__(256) void k_dw_rc(
    const float* __restrict__ wd, const float* __restrict__ bd)
{
    const int d = blockIdx.x * 256 + threadIdx.x;
    const int c = blockIdx.y;   // 0..63
    const int b = blockIdx.z;   // 0..15

    float w[KS];
    #pragma unroll
    for (int k = 0; k < KS; k++) w[k] = wd[(size_t)d * KS + k];

    float s[38];
    const int base_t = R_LEN + (c + 1) * CHUNK - CS;
    #pragma unroll
    for (int p = 0; p < 30; p++)
        s[p] = g_glu[((size_t)(base_t + p) * B_SZ + b) * D_CH + d];
    #pragma unroll
    for (int p = 0; p < 8; p++)
        s[30 + p] = g_glu[((size_t)(c * RCL + p) * B_SZ + b) * D_CH + d];

    const float bias = bd[d];
    #pragma unroll
    for (int j = 0; j < RCL; j++) {
        float acc = bias;
        #pragma unroll
        for (int k = 0; k < KS; k++) acc += w[k] * s[j + k];
        const float r = acc * sigmoidf_(acc - 1.0f);
        const int tg = c * RCL + j;
        g_z[((size_t)tg * B_SZ + b) * D_CH + d] = r;
    }
}

// ---------------------------------------------------------------------------
// Kernel 3: new_cache slice
// ---------------------------------------------------------------------------
__global__ void k_cache(float* __restrict__ out)
{
    const int e = blockIdx.x * 256 + threadIdx.x;
    if (e >= B_SZ * D_CH * CS) return;
    const int i   = e % CS;
    const int bd_ = e / CS;
    const int d   = bd_ & (D_CH - 1);
    const int b   = bd_ >> 9;
    const int tg  = T_TOT - CS + i;
    out[CACHE_OUT_OFF + e] = g_glu[((size_t)tg * B_SZ + b) * D_CH + d];
}

// ---------------------------------------------------------------------------
// Kernel 4: pointwise conv2 (D -> D) + bias, tf32 tensor-core GEMM,
// routed into final output regions. Block 128 rows x 128 out-cols.
// ---------------------------------------------------------------------------
__global__ __launch_bounds__(256) void k_gemm2(
    const float* __restrict__ w2, const float* __restrict__ b2,
    float* __restrict__ out)
{
    __shared__ unsigned As[128 * LDA];
    __shared__ unsigned Bs[128 * LDA];

    const int tid  = threadIdx.x;
    const int lane = tid & 31, warp = tid >> 5;
    const int wm   = warp >> 1;      // 0..3
    const int wn   = warp & 1;       // 0..1
    const int row0 = blockIdx.y * 128;
    const int o0   = blockIdx.x * 128;

    float acc[2][8][4];
    #pragma unroll
    for (int mi = 0; mi < 2; mi++)
        #pragma unroll
        for (int f = 0; f < 8; f++)
            #pragma unroll
            for (int q = 0; q < 4; q++) acc[mi][f][q] = 0.f;

    for (int kt = 0; kt < 16; kt++) {
        const int kbase = kt * 32;
        #pragma unroll
        for (int i = 0; i < 4; i++) {
            const int f = i * 256 + tid;
            const int r = f >> 3, kq = f & 7;
            float4 v = *(const float4*)(g_z + (size_t)(row0 + r) * D_CH + kbase + kq * 4);
            unsigned* p = &As[r * LDA + kq * 4];
            p[0] = f2tf(v.x); p[1] = f2tf(v.y); p[2] = f2tf(v.z); p[3] = f2tf(v.w);
        }
        #pragma unroll
        for (int i = 0; i < 4; i++) {
            const int f = i * 256 + tid;
            const int j = f >> 3, kq = f & 7;
            float4 v = *(const float4*)(w2 + (size_t)(o0 + j) * D_CH + kbase + kq * 4);
            unsigned* p = &Bs[j * LDA + kq * 4];
            p[0] = f2tf(v.x); p[1] = f2tf(v.y); p[2] = f2tf(v.z); p[3] = f2tf(v.w);
        }
        __syncthreads();

        #pragma unroll
        for (int ksub = 0; ksub < 4; ksub++) {
            const int k0 = ksub * 8 + (lane & 3);
            unsigned a[2][4];
            #pragma unroll
            for (int mi = 0; mi < 2; mi++) {
                const int base = (wm * 32 + mi * 16 + (lane >> 2)) * LDA + k0;
                a[mi][0] = As[base];
                a[mi][1] = As[base + 8 * LDA];
                a[mi][2] = As[base + 4];
                a[mi][3] = As[base + 8 * LDA + 4];
            }
            unsigned bf[8][2];
            #pragma unroll
            for (int f = 0; f < 8; f++) {
                const int jn = wn * 64 + f * 8 + (lane >> 2);
                bf[f][0] = Bs[jn * LDA + k0];
                bf[f][1] = Bs[jn * LDA + k0 + 4];
            }
            #pragma unroll
            for (int mi = 0; mi < 2; mi++)
                #pragma unroll
                for (int f = 0; f < 8; f++)
                    mma8(acc[mi][f], a[mi], bf[f]);
        }
        __syncthreads();
    }

    #pragma unroll
    for (int mi = 0; mi < 2; mi++) {
        #pragma unroll
        for (int rh = 0; rh < 2; rh++) {
            const int n = row0 + wm * 32 + mi * 16 + (lane >> 2) + rh * 8;
            float* dst = (n >= RB) ? (out + (size_t)(n - RB) * D_CH)
                                   : (out + UTT_OUT_ELEMS + (size_t)n * D_CH);
            #pragma unroll
            for (int f = 0; f < 8; f++) {
                const int o = o0 + wn * 64 + f * 8 + 2 * (lane & 3);
                float2 v;
                v.x = acc[mi][f][rh * 2 + 0] + b2[o];
                v.y = acc[mi][f][rh * 2 + 1] + b2[o + 1];
                *(float2*)&dst[o] = v;
            }
        }
    }
}

// ---------------------------------------------------------------------------
extern "C" void kernel_launch(void* const* d_in, const int* in_sizes, int n_in,
                              void* d_out, int out_size)
{
    const float* utt   = (const float*)d_in[0];
    const float* rc    = (const float*)d_in[1];
    const float* cache = (const float*)d_in[2];
    const float* w1    = (const float*)d_in[3];
    const float* b1    = (const float*)d_in[4];
    const float* wd    = (const float*)d_in[5];
    const float* bd    = (const float*)d_in[6];
    const float* w2    = (const float*)d_in[7];
    const float* b2    = (const float*)d_in[8];
    float* out = (float*)d_out;

    // 1) pointwise conv1 + GLU -> g_glu   (tf32 tensor cores)
    k_gemm1_glu<<<dim3(D_CH / 64, NROWS / 128), 256>>>(utt, rc, w1, b1);

    // 2) depthwise + swish -> g_z, cache slice
    k_dw_utt<<<dim3(2, U_LEN / 16, B_SZ), 256>>>(cache, wd, bd);
    k_dw_rc <<<dim3(2, NCHUNK, B_SZ), 256>>>(wd, bd);
    k_cache<<<(B_SZ * D_CH * CS + 255) / 256, 256>>>(out);

    // 3) pointwise conv2 + bias -> final outputs (tf32 tensor cores)
    k_gemm2<<<dim3(D_CH / 128, NROWS / 128), 256>>>(w2, b2, out);
}

// round 10
// speedup vs baseline: 2.5845x; 1.3462x over previous
#include <cuda_runtime.h>
#include <cstdint>
#include <math.h>

// Problem constants (fixed shapes)
#define U_LEN   2048
#define B_SZ    16
#define D_CH    512
#define R_LEN   512
#define T_TOT   2560
#define NROWS   40960
#define CS      30
#define KS      31
#define CHUNK   32
#define RCL     8
#define NCHUNK  64
#define RB      (R_LEN * B_SZ)      // 8192

#define UTT_OUT_ELEMS ((size_t)U_LEN * B_SZ * D_CH)
#define RC_OUT_ELEMS  ((size_t)R_LEN * B_SZ * D_CH)
#define CACHE_OUT_OFF (UTT_OUT_ELEMS + RC_OUT_ELEMS)

#define LDA 36            // smem row stride (words); (4k + 4rg) pattern -> conflict-free
#define ABUF_W (128 * LDA)           // 4608 words per buffer
#define SMEM_WORDS (4 * ABUF_W)      // A0 A1 B0 B1
#define SMEM_BYTES (SMEM_WORDS * 4)  // 73728

// Scratch
__device__ float g_glu[(size_t)NROWS * D_CH];
__device__ float g_z[(size_t)NROWS * D_CH];

static __device__ __forceinline__ float sigmoidf_(float x) {
    return 1.0f / (1.0f + __expf(-x));
}
static __device__ __forceinline__ unsigned f2tf(float x) {
    unsigned y; asm("cvt.rna.tf32.f32 %0, %1;" : "=r"(y) : "f"(x)); return y;
}
static __device__ __forceinline__ void mma8(float* c, const unsigned* a, const unsigned* b) {
    asm volatile(
        "mma.sync.aligned.m16n8k8.row.col.f32.tf32.tf32.f32 "
        "{%0,%1,%2,%3},{%4,%5,%6,%7},{%8,%9},{%0,%1,%2,%3};"
        : "+f"(c[0]), "+f"(c[1]), "+f"(c[2]), "+f"(c[3])
        : "r"(a[0]), "r"(a[1]), "r"(a[2]), "r"(a[3]), "r"(b[0]), "r"(b[1]));
}

// ---------------------------------------------------------------------------
// Kernel 1: pointwise conv1 (D -> 2D) + GLU, tf32 mma.sync, double-buffered
// software pipeline. Block: 128 rows x 64 d-cols (B-tile = 64 'a' + 64 'g'
// rows of W1). 8 warps (4m x 2n); warp n-frags 0..3 = a, 4..7 = g (same d),
// GLU fused in registers.
// ---------------------------------------------------------------------------
__global__ __launch_bounds__(256) void k_gemm1_glu(
    const float* __restrict__ utt, const float* __restrict__ rc,
    const float* __restrict__ w1, const float* __restrict__ b1)
{
    extern __shared__ unsigned smem_u[];

    const int tid  = threadIdx.x;
    const int lane = tid & 31, warp = tid >> 5;
    const int wm   = warp >> 1;      // 0..3
    const int wn   = warp & 1;       // 0..1
    const int row0 = blockIdx.y * 128;
    const int c0   = blockIdx.x * 64;

    // Per-thread staging: 4 fragments of (row r, 4 k's) for A and for B.
    const float* asrc[4];
    const float* bsrc[4];
    int soff[4];
    #pragma unroll
    for (int i = 0; i < 4; i++) {
        const int f = i * 256 + tid;
        const int r = f >> 3, kq = f & 7;
        const int n = row0 + r;
        asrc[i] = ((n < RB) ? (rc + (size_t)n * D_CH)
                            : (utt + (size_t)(n - RB) * D_CH)) + kq * 4;
        const int wr = (r < 64) ? (c0 + r) : (D_CH + c0 + (r - 64));
        bsrc[i] = w1 + (size_t)wr * D_CH + kq * 4;
        soff[i] = r * LDA + kq * 4;
    }

    float4 pa[4], pb[4];
    #pragma unroll
    for (int i = 0; i < 4; i++) { pa[i] = *(const float4*)asrc[i]; pb[i] = *(const float4*)bsrc[i]; }

    float acc[2][8][4];
    #pragma unroll
    for (int mi = 0; mi < 2; mi++)
        #pragma unroll
        for (int f = 0; f < 8; f++)
            #pragma unroll
            for (int q = 0; q < 4; q++) acc[mi][f][q] = 0.f;

    for (int kt = 0; kt < 16; kt++) {
        unsigned* A = smem_u + (kt & 1) * ABUF_W;
        unsigned* B = smem_u + 2 * ABUF_W + (kt & 1) * ABUF_W;

        #pragma unroll
        for (int i = 0; i < 4; i++) {
            *(uint4*)&A[soff[i]] = make_uint4(f2tf(pa[i].x), f2tf(pa[i].y),
                                              f2tf(pa[i].z), f2tf(pa[i].w));
            *(uint4*)&B[soff[i]] = make_uint4(f2tf(pb[i].x), f2tf(pb[i].y),
                                              f2tf(pb[i].z), f2tf(pb[i].w));
        }
        __syncthreads();

        if (kt < 15) {
            const int kb = (kt + 1) * 32;
            #pragma unroll
            for (int i = 0; i < 4; i++) {
                pa[i] = *(const float4*)(asrc[i] + kb);
                pb[i] = *(const float4*)(bsrc[i] + kb);
            }
        }

        #pragma unroll
        for (int ksub = 0; ksub < 4; ksub++) {
            const int k0 = ksub * 8 + (lane & 3);
            unsigned a[2][4];
            #pragma unroll
            for (int mi = 0; mi < 2; mi++) {
                const int base = (wm * 32 + mi * 16 + (lane >> 2)) * LDA + k0;
                a[mi][0] = A[base];
                a[mi][1] = A[base + 8 * LDA];
                a[mi][2] = A[base + 4];
                a[mi][3] = A[base + 8 * LDA + 4];
            }
            unsigned bf[8][2];
            #pragma unroll
            for (int f = 0; f < 8; f++) {
                const int jn = ((f < 4) ? (wn * 32 + f * 8)
                                        : (64 + wn * 32 + (f - 4) * 8)) + (lane >> 2);
                bf[f][0] = B[jn * LDA + k0];
                bf[f][1] = B[jn * LDA + k0 + 4];
            }
            #pragma unroll
            for (int mi = 0; mi < 2; mi++)
                #pragma unroll
                for (int f = 0; f < 8; f++)
                    mma8(acc[mi][f], a[mi], bf[f]);
        }
        // no trailing sync: next iteration writes the other buffer, and its
        // barrier orders reuse of this one two iterations out.
    }

    // Epilogue: GLU in registers (a-frag f pairs with g-frag f+4, same d)
    #pragma unroll
    for (int mi = 0; mi < 2; mi++) {
        #pragma unroll
        for (int rh = 0; rh < 2; rh++) {
            const int row = row0 + wm * 32 + mi * 16 + (lane >> 2) + rh * 8;
            #pragma unroll
            for (int f = 0; f < 4; f++) {
                const int d = c0 + wn * 32 + f * 8 + 2 * (lane & 3);
                const float a0 = acc[mi][f][rh * 2 + 0] + b1[d];
                const float a1 = acc[mi][f][rh * 2 + 1] + b1[d + 1];
                const float g0 = acc[mi][f + 4][rh * 2 + 0] + b1[D_CH + d];
                const float g1 = acc[mi][f + 4][rh * 2 + 1] + b1[D_CH + d + 1];
                float2 o;
                o.x = a0 * sigmoidf_(g0);
                o.y = a1 * sigmoidf_(g1);
                *(float2*)&g_glu[(size_t)row * D_CH + d] = o;
            }
        }
    }
}

// ---------------------------------------------------------------------------
// Kernel 4: pointwise conv2 (D -> D) + bias, tf32 mma.sync, same pipeline.
// Block 128 rows x 128 out-cols, routed into final output regions.
// ---------------------------------------------------------------------------
__global__ __launch_bounds__(256) void k_gemm2(
    const float* __restrict__ w2, const float* __restrict__ b2,
    float* __restrict__ out)
{
    extern __shared__ unsigned smem_u[];

    const int tid  = threadIdx.x;
    const int lane = tid & 31, warp = tid >> 5;
    const int wm   = warp >> 1;
    const int wn   = warp & 1;
    const int row0 = blockIdx.y * 128;
    const int o0   = blockIdx.x * 128;

    const float* asrc[4];
    const float* bsrc[4];
    int soff[4];
    #pragma unroll
    for (int i = 0; i < 4; i++) {
        const int f = i * 256 + tid;
        const int r = f >> 3, kq = f & 7;
        asrc[i] = g_z + (size_t)(row0 + r) * D_CH + kq * 4;
        bsrc[i] = w2  + (size_t)(o0 + r)  * D_CH + kq * 4;
        soff[i] = r * LDA + kq * 4;
    }

    float4 pa[4], pb[4];
    #pragma unroll
    for (int i = 0; i < 4; i++) { pa[i] = *(const float4*)asrc[i]; pb[i] = *(const float4*)bsrc[i]; }

    float acc[2][8][4];
    #pragma unroll
    for (int mi = 0; mi < 2; mi++)
        #pragma unroll
        for (int f = 0; f < 8; f++)
            #pragma unroll
            for (int q = 0; q < 4; q++) acc[mi][f][q] = 0.f;

    for (int kt = 0; kt < 16; kt++) {
        unsigned* A = smem_u + (kt & 1) * ABUF_W;
        unsigned* B = smem_u + 2 * ABUF_W + (kt & 1) * ABUF_W;

        #pragma unroll
        for (int i = 0; i < 4; i++) {
            *(uint4*)&A[soff[i]] = make_uint4(f2tf(pa[i].x), f2tf(pa[i].y),
                                              f2tf(pa[i].z), f2tf(pa[i].w));
            *(uint4*)&B[soff[i]] = make_uint4(f2tf(pb[i].x), f2tf(pb[i].y),
                                              f2tf(pb[i].z), f2tf(pb[i].w));
        }
        __syncthreads();

        if (kt < 15) {
            const int kb = (kt + 1) * 32;
            #pragma unroll
            for (int i = 0; i < 4; i++) {
                pa[i] = *(const float4*)(asrc[i] + kb);
                pb[i] = *(const float4*)(bsrc[i] + kb);
            }
        }

        #pragma unroll
        for (int ksub = 0; ksub < 4; ksub++) {
            const int k0 = ksub * 8 + (lane & 3);
            unsigned a[2][4];
            #pragma unroll
            for (int mi = 0; mi < 2; mi++) {
                const int base = (wm * 32 + mi * 16 + (lane >> 2)) * LDA + k0;
                a[mi][0] = A[base];
                a[mi][1] = A[base + 8 * LDA];
                a[mi][2] = A[base + 4];
                a[mi][3] = A[base + 8 * LDA + 4];
            }
            unsigned bf[8][2];
            #pragma unroll
            for (int f = 0; f < 8; f++) {
                const int jn = wn * 64 + f * 8 + (lane >> 2);
                bf[f][0] = B[jn * LDA + k0];
                bf[f][1] = B[jn * LDA + k0 + 4];
            }
            #pragma unroll
            for (int mi = 0; mi < 2; mi++)
                #pragma unroll
                for (int f = 0; f < 8; f++)
                    mma8(acc[mi][f], a[mi], bf[f]);
        }
    }

    #pragma unroll
    for (int mi = 0; mi < 2; mi++) {
        #pragma unroll
        for (int rh = 0; rh < 2; rh++) {
            const int n = row0 + wm * 32 + mi * 16 + (lane >> 2) + rh * 8;
            float* dst = (n >= RB) ? (out + (size_t)(n - RB) * D_CH)
                                   : (out + UTT_OUT_ELEMS + (size_t)n * D_CH);
            #pragma unroll
            for (int f = 0; f < 8; f++) {
                const int o = o0 + wn * 64 + f * 8 + 2 * (lane & 3);
                float2 v;
                v.x = acc[mi][f][rh * 2 + 0] + b2[o];
                v.y = acc[mi][f][rh * 2 + 1] + b2[o + 1];
                *(float2*)&dst[o] = v;
            }
        }
    }
}

// ---------------------------------------------------------------------------
// Depthwise conv (utterance) + swish -> g_z rows t>=512. 32 t's per thread.
// ---------------------------------------------------------------------------
#define TT 32
__global__ __launch_bounds__(256) void k_dw_utt(
    const float* __restrict__ cache,
    const float* __restrict__ wd, const float* __restrict__ bd)
{
    const int d  = blockIdx.x * 256 + threadIdx.x;
    const int t0 = blockIdx.y * TT;
    const int b  = blockIdx.z;

    float w[KS];
    #pragma unroll
    for (int k = 0; k < KS; k++) w[k] = wd[(size_t)d * KS + k];

    float s[TT + CS];
    #pragma unroll
    for (int p = 0; p < TT + CS; p++) {
        const int pp = t0 + p;
        if (pp < CS)
            s[p] = cache[((size_t)b * D_CH + d) * CS + pp];
        else
            s[p] = g_glu[((size_t)(R_LEN + pp - CS) * B_SZ + b) * D_CH + d];
    }

    const float bias = bd[d];
    #pragma unroll
    for (int j = 0; j < TT; j++) {
        float acc = bias;
        #pragma unroll
        for (int k = 0; k < KS; k++) acc += w[k] * s[j + k];
        const float r = acc * sigmoidf_(acc - 1.0f);
        const int tg = R_LEN + t0 + j;
        g_z[((size_t)tg * B_SZ + b) * D_CH + d] = r;
    }
}

// ---------------------------------------------------------------------------
// Depthwise conv (right-context chunks) + swish -> g_z rows t<512.
// ---------------------------------------------------------------------------
__global__ __launch_bounds__(256) void k_dw_rc(
    const float* __restrict__ wd, const float* __restrict__ bd)
{
    const int d = blockIdx.x * 256 + threadIdx.x;
    const int c = blockIdx.y;
    const int b = blockIdx.z;

    float w[KS];
    #pragma unroll
    for (int k = 0; k < KS; k++) w[k] = wd[(size_t)d * KS + k];

    float s[38];
    const int base_t = R_LEN + (c + 1) * CHUNK - CS;
    #pragma unroll
    for (int p = 0; p < 30; p++)
        s[p] = g_glu[((size_t)(base_t + p) * B_SZ + b) * D_CH + d];
    #pragma unroll
    for (int p = 0; p < 8; p++)
        s[30 + p] = g_glu[((size_t)(c * RCL + p) * B_SZ + b) * D_CH + d];

    const float bias = bd[d];
    #pragma unroll
    for (int j = 0; j < RCL; j++) {
        float acc = bias;
        #pragma unroll
        for (int k = 0; k < KS; k++) acc += w[k] * s[j + k];
        const float r = acc * sigmoidf_(acc - 1.0f);
        const int tg = c * RCL + j;
        g_z[((size_t)tg * B_SZ + b) * D_CH + d] = r;
    }
}

// ---------------------------------------------------------------------------
// new_cache slice
// ---------------------------------------------------------------------------
__global__ void k_cache(float* __restrict__ out)
{
    const int e = blockIdx.x * 256 + threadIdx.x;
    if (e >= B_SZ * D_CH * CS) return;
    const int i   = e % CS;
    const int bd_ = e / CS;
    const int d   = bd_ & (D_CH - 1);
    const int b   = bd_ >> 9;
    const int tg  = T_TOT - CS + i;
    out[CACHE_OUT_OFF + e] = g_glu[((size_t)tg * B_SZ + b) * D_CH + d];
}

// ---------------------------------------------------------------------------
extern "C" void kernel_launch(void* const* d_in, const int* in_sizes, int n_in,
                              void* d_out, int out_size)
{
    const float* utt   = (const float*)d_in[0];
    const float* rc    = (const float*)d_in[1];
    const float* cache = (const float*)d_in[2];
    const float* w1    = (const float*)d_in[3];
    const float* b1    = (const float*)d_in[4];
    const float* wd    = (const float*)d_in[5];
    const float* bd    = (const float*)d_in[6];
    const float* w2    = (const float*)d_in[7];
    const float* b2    = (const float*)d_in[8];
    float* out = (float*)d_out;

    cudaFuncSetAttribute(k_gemm1_glu, cudaFuncAttributeMaxDynamicSharedMemorySize, SMEM_BYTES);
    cudaFuncSetAttribute(k_gemm2,     cudaFuncAttributeMaxDynamicSharedMemorySize, SMEM_BYTES);

    // 1) pointwise conv1 + GLU -> g_glu  (pipelined tf32 mma.sync)
    k_gemm1_glu<<<dim3(D_CH / 64, NROWS / 128), 256, SMEM_BYTES>>>(utt, rc, w1, b1);

    // 2) depthwise + swish -> g_z, cache slice
    k_dw_utt<<<dim3(2, U_LEN / TT, B_SZ), 256>>>(cache, wd, bd);
    k_dw_rc <<<dim3(2, NCHUNK, B_SZ), 256>>>(wd, bd);
    k_cache<<<(B_SZ * D_CH * CS + 255) / 256, 256>>>(out);

    // 3) pointwise conv2 + bias -> final outputs (pipelined tf32 mma.sync)
    k_gemm2<<<dim3(D_CH / 128, NROWS / 128), 256, SMEM_BYTES>>>(w2, b2, out);
}

// round 11
// speedup vs baseline: 2.7223x; 1.0533x over previous
#include <cuda_runtime.h>
#include <cstdint>
#include <math.h>

// Problem constants (fixed shapes)
#define U_LEN   2048
#define B_SZ    16
#define D_CH    512
#define R_LEN   512
#define T_TOT   2560
#define NROWS   40960
#define CS      30
#define KS      31
#define CHUNK   32
#define RCL     8
#define NCHUNK  64
#define RB      (R_LEN * B_SZ)      // 8192

#define UTT_OUT_ELEMS ((size_t)U_LEN * B_SZ * D_CH)
#define RC_OUT_ELEMS  ((size_t)R_LEN * B_SZ * D_CH)
#define CACHE_OUT_OFF (UTT_OUT_ELEMS + RC_OUT_ELEMS)

#define LDA 36                    // smem row stride (words) -> conflict-free frags
#define A_WORDS   (128 * LDA)     // 4608
#define B_WORDS   (256 * LDA)     // 9216
#define STG_WORDS (A_WORDS + B_WORDS)   // 13824
#define STG_BYTES (STG_WORDS * 4)       // 55296
#define NSTG 3
#define SMEM_BYTES (NSTG * STG_BYTES)   // 165888

// Scratch (static device arrays)
__device__ float g_glu[(size_t)NROWS * D_CH];
__device__ float g_z[(size_t)NROWS * D_CH];
__device__ float g_a[(size_t)NROWS * D_CH];        // pre-rounded GEMM1 A
__device__ float g_w1[(size_t)2 * D_CH * D_CH];    // pre-rounded + a/g-interleaved W1
__device__ float g_w2[(size_t)D_CH * D_CH];        // pre-rounded W2

static __device__ __forceinline__ float sigmoidf_(float x) {
    return 1.0f / (1.0f + __expf(-x));
}
static __device__ __forceinline__ unsigned f2tf(float x) {
    unsigned y; asm("cvt.rna.tf32.f32 %0, %1;" : "=r"(y) : "f"(x)); return y;
}
static __device__ __forceinline__ float f2tf_f(float x) {
    return __uint_as_float(f2tf(x));
}
static __device__ __forceinline__ void mma8(float* c, const unsigned* a, const unsigned* b) {
    asm volatile(
        "mma.sync.aligned.m16n8k8.row.col.f32.tf32.tf32.f32 "
        "{%0,%1,%2,%3},{%4,%5,%6,%7},{%8,%9},{%0,%1,%2,%3};"
        : "+f"(c[0]), "+f"(c[1]), "+f"(c[2]), "+f"(c[3])
        : "r"(a[0]), "r"(a[1]), "r"(a[2]), "r"(a[3]), "r"(b[0]), "r"(b[1]));
}
static __device__ __forceinline__ void cpa16(unsigned dst, const float* src) {
    asm volatile("cp.async.cg.shared.global [%0], [%1], 16;" :: "r"(dst), "l"(src));
}
static __device__ __forceinline__ void cp_commit() {
    asm volatile("cp.async.commit_group;" ::: "memory");
}
static __device__ __forceinline__ void cp_wait1() {
    asm volatile("cp.async.wait_group 1;" ::: "memory");
}

// ---------------------------------------------------------------------------
// Pre-round kernels: utt/rc -> g_a ; w1 (interleaved a/g) -> g_w1 ; w2 -> g_w2
// ---------------------------------------------------------------------------
__global__ __launch_bounds__(256) void k_round_a(
    const float* __restrict__ utt, const float* __restrict__ rc)
{
    const int idx = blockIdx.x * 256 + threadIdx.x;      // float4 index
    const int n = idx >> 7, q = idx & 127;
    const float* src = (n < RB) ? (rc + (size_t)n * D_CH)
                                : (utt + (size_t)(n - RB) * D_CH);
    float4 v = *(const float4*)(src + q * 4);
    v.x = f2tf_f(v.x); v.y = f2tf_f(v.y); v.z = f2tf_f(v.z); v.w = f2tf_f(v.w);
    *(float4*)&g_a[(size_t)n * D_CH + q * 4] = v;
}

__global__ __launch_bounds__(256) void k_round_w(
    const float* __restrict__ w1, const float* __restrict__ w2)
{
    const int idx = blockIdx.x * 256 + threadIdx.x;      // float4 index
    if (idx < 131072) {            // g_w1: 1024 rows; even J='a' row J/2, odd J='g' row 512+J/2
        const int J = idx >> 7, q = idx & 127;
        const int sr = (J & 1) ? (D_CH + (J >> 1)) : (J >> 1);
        float4 v = *(const float4*)(w1 + (size_t)sr * D_CH + q * 4);
        v.x = f2tf_f(v.x); v.y = f2tf_f(v.y); v.z = f2tf_f(v.z); v.w = f2tf_f(v.w);
        *(float4*)&g_w1[(size_t)J * D_CH + q * 4] = v;
    } else {
        const int i2 = idx - 131072;
        if (i2 < 65536) {
            const int r = i2 >> 7, q = i2 & 127;
            float4 v = *(const float4*)(w2 + (size_t)r * D_CH + q * 4);
            v.x = f2tf_f(v.x); v.y = f2tf_f(v.y); v.z = f2tf_f(v.z); v.w = f2tf_f(v.w);
            *(float4*)&g_w2[(size_t)r * D_CH + q * 4] = v;
        }
    }
}

// ---------------------------------------------------------------------------
// Unified tcgen-free tf32 GEMM core: M=128 rows x 256 B-rows, K=512 in 16
// chunks of 32, 3-stage cp.async pipeline. 8 warps as 2m x 4n; warp tile
// 64m x 64n (mi=4, nf=8).
// MODE 0: GLU-fused conv1 (B = g_w1 interleaved a/g), writes g_glu.
// MODE 1: conv2 + bias (B = g_w2), routed into output regions.
// ---------------------------------------------------------------------------
template<int MODE>
__global__ __launch_bounds__(256) void k_gemm(
    const float* __restrict__ bias, float* __restrict__ out)
{
    extern __shared__ unsigned smem_u[];

    const int tid  = threadIdx.x;
    const int lane = tid & 31, warp = tid >> 5;
    const int wm   = warp >> 2;      // 0..1
    const int wn   = warp & 3;       // 0..3
    const int row0 = blockIdx.y * 128;
    const int c0   = blockIdx.x * (MODE == 0 ? 128 : 256);   // d-base / o-base

    // Staging bases: thread handles rows (tid>>3) + i*32, k-quad (tid&7).
    const int tr = tid >> 3, tk = tid & 7;
    const float* aBase = (MODE == 0 ? g_a : g_z)
                       + (size_t)(row0 + tr) * D_CH + tk * 4;
    const float* bBase = (MODE == 0 ? (g_w1 + (size_t)(2 * c0) * D_CH)
                                    : (g_w2 + (size_t)c0 * D_CH))
                       + (size_t)tr * D_CH + tk * 4;
    const unsigned sbase = (unsigned)__cvta_generic_to_shared(smem_u);
    const unsigned dA = sbase + (unsigned)(tr * LDA + tk * 4) * 4;
    const unsigned dB = dA + A_WORDS * 4;

    // prologue: stages 0,1
    #pragma unroll
    for (int s = 0; s < 2; s++) {
        const unsigned so = (unsigned)(s * STG_BYTES);
        #pragma unroll
        for (int i = 0; i < 4; i++)
            cpa16(dA + so + i * (32 * LDA * 4), aBase + s * 32 + i * (32 * D_CH));
        #pragma unroll
        for (int i = 0; i < 8; i++)
            cpa16(dB + so + i * (32 * LDA * 4), bBase + s * 32 + i * (32 * D_CH));
        cp_commit();
    }

    float acc[4][8][4];
    #pragma unroll
    for (int mi = 0; mi < 4; mi++)
        #pragma unroll
        for (int f = 0; f < 8; f++)
            #pragma unroll
            for (int q = 0; q < 4; q++) acc[mi][f][q] = 0.f;

    for (int kt = 0; kt < 16; kt++) {
        cp_wait1();
        __syncthreads();

        // issue stage kt+2 (empty commit past the end keeps wait-count invariant)
        if (kt + 2 < 16) {
            const int s = kt + 2;
            const unsigned so = (unsigned)((s % NSTG) * STG_BYTES);
            #pragma unroll
            for (int i = 0; i < 4; i++)
                cpa16(dA + so + i * (32 * LDA * 4), aBase + s * 32 + i * (32 * D_CH));
            #pragma unroll
            for (int i = 0; i < 8; i++)
                cpa16(dB + so + i * (32 * LDA * 4), bBase + s * 32 + i * (32 * D_CH));
        }
        cp_commit();

        const unsigned* A = smem_u + (kt % NSTG) * STG_WORDS;
        const unsigned* B = A + A_WORDS;

        #pragma unroll
        for (int ksub = 0; ksub < 4; ksub++) {
            const int k0 = ksub * 8 + (lane & 3);
            unsigned a[4][4];
            #pragma unroll
            for (int mi = 0; mi < 4; mi++) {
                const int base = (wm * 64 + mi * 16 + (lane >> 2)) * LDA + k0;
                a[mi][0] = A[base];
                a[mi][1] = A[base + 8 * LDA];
                a[mi][2] = A[base + 4];
                a[mi][3] = A[base + 8 * LDA + 4];
            }
            unsigned bf[8][2];
            #pragma unroll
            for (int f = 0; f < 8; f++) {
                const int jn = wn * 64 + f * 8 + (lane >> 2);
                bf[f][0] = B[jn * LDA + k0];
                bf[f][1] = B[jn * LDA + k0 + 4];
            }
            #pragma unroll
            for (int mi = 0; mi < 4; mi++)
                #pragma unroll
                for (int f = 0; f < 8; f++)
                    mma8(acc[mi][f], a[mi], bf[f]);
        }
    }

    // Epilogue
    if (MODE == 0) {
        // B-row j = wn*64 + f*8 + 2*(lane&3) + e ; d = c0 + j/2 ; e=0 -> a, e=1 -> g
        #pragma unroll
        for (int f = 0; f < 8; f++) {
            const int d = c0 + wn * 32 + f * 4 + (lane & 3);
            const float ba = bias[d];
            const float bg = bias[D_CH + d];
            #pragma unroll
            for (int mi = 0; mi < 4; mi++) {
                #pragma unroll
                for (int rh = 0; rh < 2; rh++) {
                    const int row = row0 + wm * 64 + mi * 16 + (lane >> 2) + rh * 8;
                    const float a = acc[mi][f][rh * 2 + 0] + ba;
                    const float g = acc[mi][f][rh * 2 + 1] + bg;
                    g_glu[(size_t)row * D_CH + d] = a * sigmoidf_(g);
                }
            }
        }
    } else {
        #pragma unroll
        for (int f = 0; f < 8; f++) {
            const int o = c0 + wn * 64 + f * 8 + 2 * (lane & 3);
            const float b0 = bias[o], b1v = bias[o + 1];
            #pragma unroll
            for (int mi = 0; mi < 4; mi++) {
                #pragma unroll
                for (int rh = 0; rh < 2; rh++) {
                    const int n = row0 + wm * 64 + mi * 16 + (lane >> 2) + rh * 8;
                    float* dst = (n >= RB) ? (out + (size_t)(n - RB) * D_CH)
                                           : (out + UTT_OUT_ELEMS + (size_t)n * D_CH);
                    float2 v;
                    v.x = acc[mi][f][rh * 2 + 0] + b0;
                    v.y = acc[mi][f][rh * 2 + 1] + b1v;
                    *(float2*)&dst[o] = v;
                }
            }
        }
    }
}

// ---------------------------------------------------------------------------
// Depthwise conv (utterance) + swish -> g_z rows t>=512. 32 t's per thread.
// Output pre-rounded to tf32 (GEMM2 operand) — numerics match cvt-at-staging.
// ---------------------------------------------------------------------------
#define TT 32
__global__ __launch_bounds__(256) void k_dw_utt(
    const float* __restrict__ cache,
    const float* __restrict__ wd, const float* __restrict__ bd)
{
    const int d  = blockIdx.x * 256 + threadIdx.x;
    const int t0 = blockIdx.y * TT;
    const int b  = blockIdx.z;

    float w[KS];
    #pragma unroll
    for (int k = 0; k < KS; k++) w[k] = wd[(size_t)d * KS + k];

    float s[TT + CS];
    #pragma unroll
    for (int p = 0; p < TT + CS; p++) {
        const int pp = t0 + p;
        if (pp < CS)
            s[p] = cache[((size_t)b * D_CH + d) * CS + pp];
        else
            s[p] = g_glu[((size_t)(R_LEN + pp - CS) * B_SZ + b) * D_CH + d];
    }

    const float bias = bd[d];
    #pragma unroll
    for (int j = 0; j < TT; j++) {
        float acc = bias;
        #pragma unroll
        for (int k = 0; k < KS; k++) acc += w[k] * s[j + k];
        const float r = acc * sigmoidf_(acc - 1.0f);
        const int tg = R_LEN + t0 + j;
        g_z[((size_t)tg * B_SZ + b) * D_CH + d] = f2tf_f(r);
    }
}

// ---------------------------------------------------------------------------
// Depthwise conv (right-context chunks) + swish -> g_z rows t<512.
// ---------------------------------------------------------------------------
__global__ __launch_bounds__(256) void k_dw_rc(
    const float* __restrict__ wd, const float* __restrict__ bd)
{
    const int d = blockIdx.x * 256 + threadIdx.x;
    const int c = blockIdx.y;
    const int b = blockIdx.z;

    float w[KS];
    #pragma unroll
    for (int k = 0; k < KS; k++) w[k] = wd[(size_t)d * KS + k];

    float s[38];
    const int base_t = R_LEN + (c + 1) * CHUNK - CS;
    #pragma unroll
    for (int p = 0; p < 30; p++)
        s[p] = g_glu[((size_t)(base_t + p) * B_SZ + b) * D_CH + d];
    #pragma unroll
    for (int p = 0; p < 8; p++)
        s[30 + p] = g_glu[((size_t)(c * RCL + p) * B_SZ + b) * D_CH + d];

    const float bias = bd[d];
    #pragma unroll
    for (int j = 0; j < RCL; j++) {
        float acc = bias;
        #pragma unroll
        for (int k = 0; k < KS; k++) acc += w[k] * s[j + k];
        const float r = acc * sigmoidf_(acc - 1.0f);
        const int tg = c * RCL + j;
        g_z[((size_t)tg * B_SZ + b) * D_CH + d] = f2tf_f(r);
    }
}

// ---------------------------------------------------------------------------
// new_cache slice
// ---------------------------------------------------------------------------
__global__ void k_cache(float* __restrict__ out)
{
    const int e = blockIdx.x * 256 + threadIdx.x;
    if (e >= B_SZ * D_CH * CS) return;
    const int i   = e % CS;
    const int bd_ = e / CS;
    const int d   = bd_ & (D_CH - 1);
    const int b   = bd_ >> 9;
    const int tg  = T_TOT - CS + i;
    out[CACHE_OUT_OFF + e] = g_glu[((size_t)tg * B_SZ + b) * D_CH + d];
}

// ---------------------------------------------------------------------------
extern "C" void kernel_launch(void* const* d_in, const int* in_sizes, int n_in,
                              void* d_out, int out_size)
{
    const float* utt   = (const float*)d_in[0];
    const float* rc    = (const float*)d_in[1];
    const float* cache = (const float*)d_in[2];
    const float* w1    = (const float*)d_in[3];
    const float* b1    = (const float*)d_in[4];
    const float* wd    = (const float*)d_in[5];
    const float* bd    = (const float*)d_in[6];
    const float* w2    = (const float*)d_in[7];
    const float* b2    = (const float*)d_in[8];
    float* out = (float*)d_out;

    cudaFuncSetAttribute(k_gemm<0>, cudaFuncAttributeMaxDynamicSharedMemorySize, SMEM_BYTES);
    cudaFuncSetAttribute(k_gemm<1>, cudaFuncAttributeMaxDynamicSharedMemorySize, SMEM_BYTES);

    // 0) pre-round operands to tf32 (keeps mma truncation exact)
    k_round_a<<<(NROWS * 128) / 256, 256>>>(utt, rc);       // 40960*512/4 float4
    k_round_w<<<(131072 + 65536 + 255) / 256, 256>>>(w1, w2);

    // 1) pointwise conv1 + GLU -> g_glu
    k_gemm<0><<<dim3(D_CH / 128, NROWS / 128), 256, SMEM_BYTES>>>(b1, nullptr);

    // 2) depthwise + swish -> g_z (tf32-rounded), cache slice
    k_dw_utt<<<dim3(2, U_LEN / TT, B_SZ), 256>>>(cache, wd, bd);
    k_dw_rc <<<dim3(2, NCHUNK, B_SZ), 256>>>(wd, bd);
    k_cache<<<(B_SZ * D_CH * CS + 255) / 256, 256>>>(out);

    // 3) pointwise conv2 + bias -> final outputs
    k_gemm<1><<<dim3(D_CH / 256, NROWS / 128), 256, SMEM_BYTES>>>(b2, out);
}

// round 12
// speedup vs baseline: 3.9212x; 1.4404x over previous
#include <cuda_runtime.h>
#include <cuda_fp16.h>
#include <cstdint>
#include <math.h>

// Problem constants (fixed shapes)
#define U_LEN   2048
#define B_SZ    16
#define D_CH    512
#define R_LEN   512
#define T_TOT   2560
#define NROWS   40960
#define CS      30
#define KS      31
#define CHUNK   32
#define RCL     8
#define NCHUNK  64
#define RB      (R_LEN * B_SZ)      // 8192

#define UTT_OUT_ELEMS ((size_t)U_LEN * B_SZ * D_CH)
#define RC_OUT_ELEMS  ((size_t)R_LEN * B_SZ * D_CH)
#define CACHE_OUT_OFF (UTT_OUT_ELEMS + RC_OUT_ELEMS)

// fp16 GEMM smem geometry: K-chunk = 32 halves = 16 half2 words, padded to 20
#define LDAH 20                       // words (half2) per row -> conflict-free
#define A_WORDS_H (128 * LDAH)        // 2560
#define B_WORDS_H (256 * LDAH)        // 5120
#define STG_WORDS_H (A_WORDS_H + B_WORDS_H)   // 7680
#define STG_BYTES_H (STG_WORDS_H * 4)         // 30720
#define NSTG 3
#define SMEM_BYTES_H (NSTG * STG_BYTES_H)     // 92160

// Scratch (static device arrays)
__device__ float  g_glu[(size_t)NROWS * D_CH];      // GLU output (fp32; feeds dw + cache)
__device__ __half g_ah [(size_t)NROWS * D_CH];      // fp16 GEMM1 A
__device__ __half g_zh [(size_t)NROWS * D_CH];      // fp16 dw+swish output (GEMM2 A)
__device__ __half g_w1h[(size_t)2 * D_CH * D_CH];   // fp16, a/g-interleaved W1
__device__ __half g_w2h[(size_t)D_CH * D_CH];       // fp16 W2

static __device__ __forceinline__ float sigmoidf_(float x) {
    return 1.0f / (1.0f + __expf(-x));
}
static __device__ __forceinline__ void mma16(float* c, const unsigned* a, const unsigned* b) {
    asm volatile(
        "mma.sync.aligned.m16n8k16.row.col.f32.f16.f16.f32 "
        "{%0,%1,%2,%3},{%4,%5,%6,%7},{%8,%9},{%0,%1,%2,%3};"
        : "+f"(c[0]), "+f"(c[1]), "+f"(c[2]), "+f"(c[3])
        : "r"(a[0]), "r"(a[1]), "r"(a[2]), "r"(a[3]), "r"(b[0]), "r"(b[1]));
}
static __device__ __forceinline__ void cpa16(unsigned dst, const void* src) {
    asm volatile("cp.async.cg.shared.global [%0], [%1], 16;" :: "r"(dst), "l"(src));
}
static __device__ __forceinline__ void cp_commit() {
    asm volatile("cp.async.commit_group;" ::: "memory");
}
static __device__ __forceinline__ void cp_wait1() {
    asm volatile("cp.async.wait_group 1;" ::: "memory");
}

// ---------------------------------------------------------------------------
// Pre-convert: utt/rc -> g_ah (fp16). One thread = 8 elements.
// ---------------------------------------------------------------------------
__global__ __launch_bounds__(256) void k_round_a(
    const float* __restrict__ utt, const float* __restrict__ rc)
{
    const int idx = blockIdx.x * 256 + threadIdx.x;      // 8-elem group
    const int n = idx >> 6, q = idx & 63;
    const float* src = ((n < RB) ? (rc + (size_t)n * D_CH)
                                 : (utt + (size_t)(n - RB) * D_CH)) + q * 8;
    float4 v0 = *(const float4*)src;
    float4 v1 = *(const float4*)(src + 4);
    __half2 h[4];
    h[0] = __floats2half2_rn(v0.x, v0.y);
    h[1] = __floats2half2_rn(v0.z, v0.w);
    h[2] = __floats2half2_rn(v1.x, v1.y);
    h[3] = __floats2half2_rn(v1.z, v1.w);
    *(uint4*)&g_ah[(size_t)n * D_CH + q * 8] = *(uint4*)h;
}

// w1 (a/g interleaved) -> g_w1h ; w2 -> g_w2h
__global__ __launch_bounds__(256) void k_round_w(
    const float* __restrict__ w1, const float* __restrict__ w2)
{
    const int idx = blockIdx.x * 256 + threadIdx.x;
    const float* src;
    __half* dst;
    if (idx < 65536) {        // g_w1h: 1024 rows; even J='a' row J/2, odd J='g' row 512+J/2
        const int J = idx >> 6, q = idx & 63;
        const int sr = (J & 1) ? (D_CH + (J >> 1)) : (J >> 1);
        src = w1 + (size_t)sr * D_CH + q * 8;
        dst = g_w1h + (size_t)J * D_CH + q * 8;
    } else {
        const int i2 = idx - 65536;
        if (i2 >= 32768) return;
        const int r = i2 >> 6, q = i2 & 63;
        src = w2 + (size_t)r * D_CH + q * 8;
        dst = g_w2h + (size_t)r * D_CH + q * 8;
    }
    float4 v0 = *(const float4*)src;
    float4 v1 = *(const float4*)(src + 4);
    __half2 h[4];
    h[0] = __floats2half2_rn(v0.x, v0.y);
    h[1] = __floats2half2_rn(v0.z, v0.w);
    h[2] = __floats2half2_rn(v1.x, v1.y);
    h[3] = __floats2half2_rn(v1.z, v1.w);
    *(uint4*)dst = *(uint4*)h;
}

// ---------------------------------------------------------------------------
// fp16 tensor-core GEMM: M=128 rows x 256 B-rows, K=512 in 16 chunks of 32,
// 3-stage cp.async pipeline. 8 warps as 2m x 4n; warp tile 64x64 via
// mma.m16n8k16 (mi=4, nf=8), fp32 accumulate.
// MODE 0: GLU-fused conv1 (B = g_w1h interleaved a/g), writes g_glu (fp32).
// MODE 1: conv2 + bias (B = g_w2h), routed into output regions.
// ---------------------------------------------------------------------------
template<int MODE>
__global__ __launch_bounds__(256) void k_gemm(
    const float* __restrict__ bias, float* __restrict__ out)
{
    extern __shared__ unsigned smem_u[];

    const int tid  = threadIdx.x;
    const int lane = tid & 31, warp = tid >> 5;
    const int wm   = warp >> 2;      // 0..1
    const int wn   = warp & 3;       // 0..3
    const int row0 = blockIdx.y * 128;
    const int c0   = blockIdx.x * (MODE == 0 ? 128 : 256);

    // Staging: 16B unit = 8 halves. A: 128 rows x 4 units (2/thread);
    // B: 256 rows x 4 units (4/thread). Thread -> row (tid>>2)+i*64, quarter tid&3.
    const int tr = tid >> 2, tq = tid & 3;
    const __half* aBase = (MODE == 0 ? g_ah : g_zh)
                        + (size_t)(row0 + tr) * D_CH + tq * 8;
    const __half* bBase = (MODE == 0 ? (g_w1h + (size_t)(2 * c0) * D_CH)
                                     : (g_w2h + (size_t)c0 * D_CH))
                        + (size_t)tr * D_CH + tq * 8;
    const unsigned sbase = (unsigned)__cvta_generic_to_shared(smem_u);
    const unsigned dA = sbase + (unsigned)(tr * LDAH + tq * 4) * 4;
    const unsigned dB = dA + A_WORDS_H * 4;

    // prologue: stages 0,1
    #pragma unroll
    for (int s = 0; s < 2; s++) {
        const unsigned so = (unsigned)(s * STG_BYTES_H);
        #pragma unroll
        for (int i = 0; i < 2; i++)
            cpa16(dA + so + i * (64 * LDAH * 4), aBase + s * 32 + i * (64 * D_CH));
        #pragma unroll
        for (int i = 0; i < 4; i++)
            cpa16(dB + so + i * (64 * LDAH * 4), bBase + s * 32 + i * (64 * D_CH));
        cp_commit();
    }

    float acc[4][8][4];
    #pragma unroll
    for (int mi = 0; mi < 4; mi++)
        #pragma unroll
        for (int f = 0; f < 8; f++)
            #pragma unroll
            for (int q = 0; q < 4; q++) acc[mi][f][q] = 0.f;

    for (int kt = 0; kt < 16; kt++) {
        cp_wait1();
        __syncthreads();

        if (kt + 2 < 16) {
            const int s = kt + 2;
            const unsigned so = (unsigned)((s % NSTG) * STG_BYTES_H);
            #pragma unroll
            for (int i = 0; i < 2; i++)
                cpa16(dA + so + i * (64 * LDAH * 4), aBase + s * 32 + i * (64 * D_CH));
            #pragma unroll
            for (int i = 0; i < 4; i++)
                cpa16(dB + so + i * (64 * LDAH * 4), bBase + s * 32 + i * (64 * D_CH));
        }
        cp_commit();

        const unsigned* A = smem_u + (kt % NSTG) * STG_WORDS_H;
        const unsigned* B = A + A_WORDS_H;

        #pragma unroll
        for (int ks = 0; ks < 2; ks++) {            // two k16 steps per chunk
            const int w0 = ks * 8 + (lane & 3);
            unsigned a[4][4];
            #pragma unroll
            for (int mi = 0; mi < 4; mi++) {
                const int base = (wm * 64 + mi * 16 + (lane >> 2)) * LDAH + w0;
                a[mi][0] = A[base];
                a[mi][1] = A[base + 8 * LDAH];
                a[mi][2] = A[base + 4];
                a[mi][3] = A[base + 8 * LDAH + 4];
            }
            unsigned bf[8][2];
            #pragma unroll
            for (int f = 0; f < 8; f++) {
                const int jn = wn * 64 + f * 8 + (lane >> 2);
                bf[f][0] = B[jn * LDAH + w0];
                bf[f][1] = B[jn * LDAH + w0 + 4];
            }
            #pragma unroll
            for (int mi = 0; mi < 4; mi++)
                #pragma unroll
                for (int f = 0; f < 8; f++)
                    mma16(acc[mi][f], a[mi], bf[f]);
        }
    }

    // Epilogue (C frag layout identical to k8 case)
    if (MODE == 0) {
        #pragma unroll
        for (int f = 0; f < 8; f++) {
            const int d = c0 + wn * 32 + f * 4 + (lane & 3);
            const float ba = bias[d];
            const float bg = bias[D_CH + d];
            #pragma unroll
            for (int mi = 0; mi < 4; mi++) {
                #pragma unroll
                for (int rh = 0; rh < 2; rh++) {
                    const int row = row0 + wm * 64 + mi * 16 + (lane >> 2) + rh * 8;
                    const float a = acc[mi][f][rh * 2 + 0] + ba;
                    const float g = acc[mi][f][rh * 2 + 1] + bg;
                    g_glu[(size_t)row * D_CH + d] = a * sigmoidf_(g);
                }
            }
        }
    } else {
        #pragma unroll
        for (int f = 0; f < 8; f++) {
            const int o = c0 + wn * 64 + f * 8 + 2 * (lane & 3);
            const float b0 = bias[o], b1v = bias[o + 1];
            #pragma unroll
            for (int mi = 0; mi < 4; mi++) {
                #pragma unroll
                for (int rh = 0; rh < 2; rh++) {
                    const int n = row0 + wm * 64 + mi * 16 + (lane >> 2) + rh * 8;
                    float* dst = (n >= RB) ? (out + (size_t)(n - RB) * D_CH)
                                           : (out + UTT_OUT_ELEMS + (size_t)n * D_CH);
                    float2 v;
                    v.x = acc[mi][f][rh * 2 + 0] + b0;
                    v.y = acc[mi][f][rh * 2 + 1] + b1v;
                    *(float2*)&dst[o] = v;
                }
            }
        }
    }
}

// ---------------------------------------------------------------------------
// Depthwise conv (utterance) + swish -> g_zh rows t>=512.
// Sliding 30-reg history window, 32 outputs per thread (low regs -> high occ).
// ---------------------------------------------------------------------------
#define TT 32
__global__ __launch_bounds__(256) void k_dw_utt(
    const float* __restrict__ cache,
    const float* __restrict__ wd, const float* __restrict__ bd)
{
    const int d  = blockIdx.x * 256 + threadIdx.x;
    const int t0 = blockIdx.y * TT;
    const int b  = blockIdx.z;

    float w[KS];
    #pragma unroll
    for (int k = 0; k < KS; k++) w[k] = wd[(size_t)d * KS + k];

    float h[CS];   // pad[t0 .. t0+29]
    #pragma unroll
    for (int p = 0; p < CS; p++) {
        const int pp = t0 + p;
        if (pp < CS)
            h[p] = cache[((size_t)b * D_CH + d) * CS + pp];
        else
            h[p] = g_glu[((size_t)(R_LEN + pp - CS) * B_SZ + b) * D_CH + d];
    }

    const float bias = bd[d];
    #pragma unroll
    for (int j = 0; j < TT; j++) {
        const size_t gidx = ((size_t)(R_LEN + t0 + j) * B_SZ + b) * D_CH + d;
        const float cur = g_glu[gidx];
        float acc = bias;
        #pragma unroll
        for (int k = 0; k < CS; k++) acc += w[k] * h[k];
        acc += w[CS] * cur;
        const float r = acc * sigmoidf_(acc - 1.0f);
        g_zh[gidx] = __float2half_rn(r);
        #pragma unroll
        for (int k = 0; k < CS - 1; k++) h[k] = h[k + 1];
        h[CS - 1] = cur;
    }
}

// ---------------------------------------------------------------------------
// Depthwise conv (right-context chunks) + swish -> g_zh rows t<512.
// ---------------------------------------------------------------------------
__global__ __launch_bounds__(256) void k_dw_rc(
    const float* __restrict__ wd, const float* __restrict__ bd)
{
    const int d = blockIdx.x * 256 + threadIdx.x;
    const int c = blockIdx.y;
    const int b = blockIdx.z;

    float w[KS];
    #pragma unroll
    for (int k = 0; k < KS; k++) w[k] = wd[(size_t)d * KS + k];

    float s[38];
    const int base_t = R_LEN + (c + 1) * CHUNK - CS;
    #pragma unroll
    for (int p = 0; p < 30; p++)
        s[p] = g_glu[((size_t)(base_t + p) * B_SZ + b) * D_CH + d];
    #pragma unroll
    for (int p = 0; p < 8; p++)
        s[30 + p] = g_glu[((size_t)(c * RCL + p) * B_SZ + b) * D_CH + d];

    const float bias = bd[d];
    #pragma unroll
    for (int j = 0; j < RCL; j++) {
        float acc = bias;
        #pragma unroll
        for (int k = 0; k < KS; k++) acc += w[k] * s[j + k];
        const float r = acc * sigmoidf_(acc - 1.0f);
        const int tg = c * RCL + j;
        g_zh[((size_t)tg * B_SZ + b) * D_CH + d] = __float2half_rn(r);
    }
}

// ---------------------------------------------------------------------------
// new_cache slice (full fp32 from g_glu)
// ---------------------------------------------------------------------------
__global__ void k_cache(float* __restrict__ out)
{
    const int e = blockIdx.x * 256 + threadIdx.x;
    if (e >= B_SZ * D_CH * CS) return;
    const int i   = e % CS;
    const int bd_ = e / CS;
    const int d   = bd_ & (D_CH - 1);
    const int b   = bd_ >> 9;
    const int tg  = T_TOT - CS + i;
    out[CACHE_OUT_OFF + e] = g_glu[((size_t)tg * B_SZ + b) * D_CH + d];
}

// ---------------------------------------------------------------------------
extern "C" void kernel_launch(void* const* d_in, const int* in_sizes, int n_in,
                              void* d_out, int out_size)
{
    const float* utt   = (const float*)d_in[0];
    const float* rc    = (const float*)d_in[1];
    const float* cache = (const float*)d_in[2];
    const float* w1    = (const float*)d_in[3];
    const float* b1    = (const float*)d_in[4];
    const float* wd    = (const float*)d_in[5];
    const float* bd    = (const float*)d_in[6];
    const float* w2    = (const float*)d_in[7];
    const float* b2    = (const float*)d_in[8];
    float* out = (float*)d_out;

    cudaFuncSetAttribute(k_gemm<0>, cudaFuncAttributeMaxDynamicSharedMemorySize, SMEM_BYTES_H);
    cudaFuncSetAttribute(k_gemm<1>, cudaFuncAttributeMaxDynamicSharedMemorySize, SMEM_BYTES_H);

    // 0) convert operands to fp16
    k_round_a<<<(NROWS * 64) / 256, 256>>>(utt, rc);
    k_round_w<<<(65536 + 32768) / 256, 256>>>(w1, w2);

    // 1) pointwise conv1 + GLU -> g_glu
    k_gemm<0><<<dim3(D_CH / 128, NROWS / 128), 256, SMEM_BYTES_H>>>(b1, nullptr);

    // 2) depthwise + swish -> g_zh, cache slice
    k_dw_utt<<<dim3(2, U_LEN / TT, B_SZ), 256>>>(cache, wd, bd);
    k_dw_rc <<<dim3(2, NCHUNK, B_SZ), 256>>>(wd, bd);
    k_cache<<<(B_SZ * D_CH * CS + 255) / 256, 256>>>(out);

    // 3) pointwise conv2 + bias -> final outputs
    k_gemm<1><<<dim3(D_CH / 256, NROWS / 128), 256, SMEM_BYTES_H>>>(b2, out);
}

// round 13
// speedup vs baseline: 4.3135x; 1.1001x over previous
#include <cuda_runtime.h>
#include <cuda_fp16.h>
#include <cstdint>
#include <math.h>

// Problem constants (fixed shapes)
#define U_LEN   2048
#define B_SZ    16
#define D_CH    512
#define R_LEN   512
#define T_TOT   2560
#define NROWS   40960
#define CS      30
#define KS      31
#define CHUNK   32
#define RCL     8
#define NCHUNK  64
#define RB      (R_LEN * B_SZ)      // 8192

#define UTT_OUT_ELEMS ((size_t)U_LEN * B_SZ * D_CH)
#define RC_OUT_ELEMS  ((size_t)R_LEN * B_SZ * D_CH)
#define CACHE_OUT_OFF (UTT_OUT_ELEMS + RC_OUT_ELEMS)

// fp16 GEMM smem geometry: K-chunk = 32 halves = 16 half2 words, padded to 20
#define LDAH 20                       // words (half2) per row -> conflict-free
#define A_WORDS_H (128 * LDAH)        // 2560
#define B_WORDS_H (128 * LDAH)        // 2560
#define STG_WORDS_H (A_WORDS_H + B_WORDS_H)   // 5120
#define STG_BYTES_H (STG_WORDS_H * 4)         // 20480
#define NSTG 3
#define SMEM_BYTES_H (NSTG * STG_BYTES_H)     // 61440

// Scratch (static device arrays)
__device__ float  g_glu[(size_t)NROWS * D_CH];      // GLU output (fp32; feeds dw + cache)
__device__ __half g_ah [(size_t)NROWS * D_CH];      // fp16 GEMM1 A
__device__ __half g_zh [(size_t)NROWS * D_CH];      // fp16 dw+swish output (GEMM2 A)
__device__ __half g_w1h[(size_t)2 * D_CH * D_CH];   // fp16, a/g-interleaved W1
__device__ __half g_w2h[(size_t)D_CH * D_CH];       // fp16 W2

static __device__ __forceinline__ float sigmoidf_(float x) {
    return 1.0f / (1.0f + __expf(-x));
}
static __device__ __forceinline__ void mma16(float* c, const unsigned* a, const unsigned* b) {
    asm volatile(
        "mma.sync.aligned.m16n8k16.row.col.f32.f16.f16.f32 "
        "{%0,%1,%2,%3},{%4,%5,%6,%7},{%8,%9},{%0,%1,%2,%3};"
        : "+f"(c[0]), "+f"(c[1]), "+f"(c[2]), "+f"(c[3])
        : "r"(a[0]), "r"(a[1]), "r"(a[2]), "r"(a[3]), "r"(b[0]), "r"(b[1]));
}
static __device__ __forceinline__ void cpa16(unsigned dst, const void* src) {
    asm volatile("cp.async.cg.shared.global [%0], [%1], 16;" :: "r"(dst), "l"(src));
}
static __device__ __forceinline__ void cp_commit() {
    asm volatile("cp.async.commit_group;" ::: "memory");
}
static __device__ __forceinline__ void cp_wait1() {
    asm volatile("cp.async.wait_group 1;" ::: "memory");
}

// ---------------------------------------------------------------------------
// Pre-convert: utt/rc -> g_ah (fp16). One thread = 8 elements.
// ---------------------------------------------------------------------------
__global__ __launch_bounds__(256) void k_round_a(
    const float* __restrict__ utt, const float* __restrict__ rc)
{
    const int idx = blockIdx.x * 256 + threadIdx.x;      // 8-elem group
    const int n = idx >> 6, q = idx & 63;
    const float* src = ((n < RB) ? (rc + (size_t)n * D_CH)
                                 : (utt + (size_t)(n - RB) * D_CH)) + q * 8;
    float4 v0 = *(const float4*)src;
    float4 v1 = *(const float4*)(src + 4);
    __half2 h[4];
    h[0] = __floats2half2_rn(v0.x, v0.y);
    h[1] = __floats2half2_rn(v0.z, v0.w);
    h[2] = __floats2half2_rn(v1.x, v1.y);
    h[3] = __floats2half2_rn(v1.z, v1.w);
    *(uint4*)&g_ah[(size_t)n * D_CH + q * 8] = *(uint4*)h;
}

// w1 (a/g interleaved) -> g_w1h ; w2 -> g_w2h
__global__ __launch_bounds__(256) void k_round_w(
    const float* __restrict__ w1, const float* __restrict__ w2)
{
    const int idx = blockIdx.x * 256 + threadIdx.x;
    const float* src;
    __half* dst;
    if (idx < 65536) {        // g_w1h: 1024 rows; even J='a' row J/2, odd J='g' row 512+J/2
        const int J = idx >> 6, q = idx & 63;
        const int sr = (J & 1) ? (D_CH + (J >> 1)) : (J >> 1);
        src = w1 + (size_t)sr * D_CH + q * 8;
        dst = g_w1h + (size_t)J * D_CH + q * 8;
    } else {
        const int i2 = idx - 65536;
        if (i2 >= 32768) return;
        const int r = i2 >> 6, q = i2 & 63;
        src = w2 + (size_t)r * D_CH + q * 8;
        dst = g_w2h + (size_t)r * D_CH + q * 8;
    }
    float4 v0 = *(const float4*)src;
    float4 v1 = *(const float4*)(src + 4);
    __half2 h[4];
    h[0] = __floats2half2_rn(v0.x, v0.y);
    h[1] = __floats2half2_rn(v0.z, v0.w);
    h[2] = __floats2half2_rn(v1.x, v1.y);
    h[3] = __floats2half2_rn(v1.z, v1.w);
    *(uint4*)dst = *(uint4*)h;
}

// ---------------------------------------------------------------------------
// fp16 tensor-core GEMM: CTA tile M=128 rows x 128 B-rows, K=512 in 16
// chunks of 32, 3-stage cp.async pipeline. 8 warps as 2m x 4n; warp tile
// 64x32 via mma.m16n8k16 (mi=4, nf=4), fp32 accumulate. 64-reg accumulator
// -> 2 CTAs/SM so staging/sync bubbles overlap.
// MODE 0: GLU-fused conv1 (B = g_w1h interleaved a/g), writes g_glu (fp32).
// MODE 1: conv2 + bias (B = g_w2h), routed into output regions.
// ---------------------------------------------------------------------------
template<int MODE>
__global__ __launch_bounds__(256, 2) void k_gemm(
    const float* __restrict__ bias, float* __restrict__ out)
{
    extern __shared__ unsigned smem_u[];

    const int tid  = threadIdx.x;
    const int lane = tid & 31, warp = tid >> 5;
    const int wm   = warp >> 2;      // 0..1
    const int wn   = warp & 3;       // 0..3
    const int row0 = blockIdx.y * 128;
    const int c0   = blockIdx.x * (MODE == 0 ? 64 : 128);

    // Staging: 16B unit = 8 halves. A: 128 rows x 4 units (2/thread);
    // B: 128 rows x 4 units (2/thread). Thread -> row (tid>>2)+i*64, quarter tid&3.
    const int tr = tid >> 2, tq = tid & 3;
    const __half* aBase = (MODE == 0 ? g_ah : g_zh)
                        + (size_t)(row0 + tr) * D_CH + tq * 8;
    const __half* bBase = (MODE == 0 ? (g_w1h + (size_t)(2 * c0) * D_CH)
                                     : (g_w2h + (size_t)c0 * D_CH))
                        + (size_t)tr * D_CH + tq * 8;
    const unsigned sbase = (unsigned)__cvta_generic_to_shared(smem_u);
    const unsigned dA = sbase + (unsigned)(tr * LDAH + tq * 4) * 4;
    const unsigned dB = dA + A_WORDS_H * 4;

    // prologue: stages 0,1
    #pragma unroll
    for (int s = 0; s < 2; s++) {
        const unsigned so = (unsigned)(s * STG_BYTES_H);
        #pragma unroll
        for (int i = 0; i < 2; i++)
            cpa16(dA + so + i * (64 * LDAH * 4), aBase + s * 32 + i * (64 * D_CH));
        #pragma unroll
        for (int i = 0; i < 2; i++)
            cpa16(dB + so + i * (64 * LDAH * 4), bBase + s * 32 + i * (64 * D_CH));
        cp_commit();
    }

    float acc[4][4][4];
    #pragma unroll
    for (int mi = 0; mi < 4; mi++)
        #pragma unroll
        for (int f = 0; f < 4; f++)
            #pragma unroll
            for (int q = 0; q < 4; q++) acc[mi][f][q] = 0.f;

    for (int kt = 0; kt < 16; kt++) {
        cp_wait1();
        __syncthreads();

        if (kt + 2 < 16) {
            const int s = kt + 2;
            const unsigned so = (unsigned)((s % NSTG) * STG_BYTES_H);
            #pragma unroll
            for (int i = 0; i < 2; i++)
                cpa16(dA + so + i * (64 * LDAH * 4), aBase + s * 32 + i * (64 * D_CH));
            #pragma unroll
            for (int i = 0; i < 2; i++)
                cpa16(dB + so + i * (64 * LDAH * 4), bBase + s * 32 + i * (64 * D_CH));
        }
        cp_commit();

        const unsigned* A = smem_u + (kt % NSTG) * STG_WORDS_H;
        const unsigned* B = A + A_WORDS_H;

        #pragma unroll
        for (int ks = 0; ks < 2; ks++) {            // two k16 steps per chunk
            const int w0 = ks * 8 + (lane & 3);
            unsigned a[4][4];
            #pragma unroll
            for (int mi = 0; mi < 4; mi++) {
                const int base = (wm * 64 + mi * 16 + (lane >> 2)) * LDAH + w0;
                a[mi][0] = A[base];
                a[mi][1] = A[base + 8 * LDAH];
                a[mi][2] = A[base + 4];
                a[mi][3] = A[base + 8 * LDAH + 4];
            }
            unsigned bf[4][2];
            #pragma unroll
            for (int f = 0; f < 4; f++) {
                const int jn = wn * 32 + f * 8 + (lane >> 2);
                bf[f][0] = B[jn * LDAH + w0];
                bf[f][1] = B[jn * LDAH + w0 + 4];
            }
            #pragma unroll
            for (int mi = 0; mi < 4; mi++)
                #pragma unroll
                for (int f = 0; f < 4; f++)
                    mma16(acc[mi][f], a[mi], bf[f]);
        }
    }

    // Epilogue
    if (MODE == 0) {
        // B-row j = wn*32 + f*8 + 2*(lane&3) + e ; d = c0 + j/2 ; e=0 -> a, e=1 -> g
        #pragma unroll
        for (int f = 0; f < 4; f++) {
            const int d = c0 + wn * 16 + f * 4 + (lane & 3);
            const float ba = bias[d];
            const float bg = bias[D_CH + d];
            #pragma unroll
            for (int mi = 0; mi < 4; mi++) {
                #pragma unroll
                for (int rh = 0; rh < 2; rh++) {
                    const int row = row0 + wm * 64 + mi * 16 + (lane >> 2) + rh * 8;
                    const float a = acc[mi][f][rh * 2 + 0] + ba;
                    const float g = acc[mi][f][rh * 2 + 1] + bg;
                    g_glu[(size_t)row * D_CH + d] = a * sigmoidf_(g);
                }
            }
        }
    } else {
        #pragma unroll
        for (int f = 0; f < 4; f++) {
            const int o = c0 + wn * 32 + f * 8 + 2 * (lane & 3);
            const float b0 = bias[o], b1v = bias[o + 1];
            #pragma unroll
            for (int mi = 0; mi < 4; mi++) {
                #pragma unroll
                for (int rh = 0; rh < 2; rh++) {
                    const int n = row0 + wm * 64 + mi * 16 + (lane >> 2) + rh * 8;
                    float* dst = (n >= RB) ? (out + (size_t)(n - RB) * D_CH)
                                           : (out + UTT_OUT_ELEMS + (size_t)n * D_CH);
                    float2 v;
                    v.x = acc[mi][f][rh * 2 + 0] + b0;
                    v.y = acc[mi][f][rh * 2 + 1] + b1v;
                    *(float2*)&dst[o] = v;
                }
            }
        }
    }
}

// ---------------------------------------------------------------------------
// Depthwise conv (utterance) + swish -> g_zh rows t>=512.
// Sliding 30-reg history window, 32 outputs/thread, 4-way split accumulators
// (FMA dependency chain 124 -> ~44 cyc).
// ---------------------------------------------------------------------------
#define TT 32
__global__ __launch_bounds__(256) void k_dw_utt(
    const float* __restrict__ cache,
    const float* __restrict__ wd, const float* __restrict__ bd)
{
    const int d  = blockIdx.x * 256 + threadIdx.x;
    const int t0 = blockIdx.y * TT;
    const int b  = blockIdx.z;

    float w[KS];
    #pragma unroll
    for (int k = 0; k < KS; k++) w[k] = wd[(size_t)d * KS + k];

    float h[CS];   // pad[t0 .. t0+29]
    #pragma unroll
    for (int p = 0; p < CS; p++) {
        const int pp = t0 + p;
        if (pp < CS)
            h[p] = cache[((size_t)b * D_CH + d) * CS + pp];
        else
            h[p] = g_glu[((size_t)(R_LEN + pp - CS) * B_SZ + b) * D_CH + d];
    }

    const float bias = bd[d];
    #pragma unroll
    for (int j = 0; j < TT; j++) {
        const size_t gidx = ((size_t)(R_LEN + t0 + j) * B_SZ + b) * D_CH + d;
        const float cur = g_glu[gidx];
        float s0 = bias, s1 = 0.f, s2 = 0.f, s3 = 0.f;
        #pragma unroll
        for (int k = 0; k < 28; k += 4) {
            s0 += w[k + 0] * h[k + 0];
            s1 += w[k + 1] * h[k + 1];
            s2 += w[k + 2] * h[k + 2];
            s3 += w[k + 3] * h[k + 3];
        }
        s0 += w[28] * h[28];
        s1 += w[29] * h[29];
        s2 += w[30] * cur;
        const float acc = (s0 + s1) + (s2 + s3);
        const float r = acc * sigmoidf_(acc - 1.0f);
        g_zh[gidx] = __float2half_rn(r);
        #pragma unroll
        for (int k = 0; k < CS - 1; k++) h[k] = h[k + 1];
        h[CS - 1] = cur;
    }
}

// ---------------------------------------------------------------------------
// Depthwise conv (right-context chunks) + swish -> g_zh rows t<512.
// ---------------------------------------------------------------------------
__global__ __launch_bounds__(256) void k_dw_rc(
    const float* __restrict__ wd, const float* __restrict__ bd)
{
    const int d = blockIdx.x * 256 + threadIdx.x;
    const int c = blockIdx.y;
    const int b = blockIdx.z;

    float w[KS];
    #pragma unroll
    for (int k = 0; k < KS; k++) w[k] = wd[(size_t)d * KS + k];

    float s[38];
    const int base_t = R_LEN + (c + 1) * CHUNK - CS;
    #pragma unroll
    for (int p = 0; p < 30; p++)
        s[p] = g_glu[((size_t)(base_t + p) * B_SZ + b) * D_CH + d];
    #pragma unroll
    for (int p = 0; p < 8; p++)
        s[30 + p] = g_glu[((size_t)(c * RCL + p) * B_SZ + b) * D_CH + d];

    const float bias = bd[d];
    #pragma unroll
    for (int j = 0; j < RCL; j++) {
        float s0 = bias, s1 = 0.f, s2 = 0.f, s3 = 0.f;
        #pragma unroll
        for (int k = 0; k < 28; k += 4) {
            s0 += w[k + 0] * s[j + k + 0];
            s1 += w[k + 1] * s[j + k + 1];
            s2 += w[k + 2] * s[j + k + 2];
            s3 += w[k + 3] * s[j + k + 3];
        }
        s0 += w[28] * s[j + 28];
        s1 += w[29] * s[j + 29];
        s2 += w[30] * s[j + 30];
        const float acc = (s0 + s1) + (s2 + s3);
        const float r = acc * sigmoidf_(acc - 1.0f);
        const int tg = c * RCL + j;
        g_zh[((size_t)tg * B_SZ + b) * D_CH + d] = __float2half_rn(r);
    }
}

// ---------------------------------------------------------------------------
// new_cache slice (full fp32 from g_glu)
// ---------------------------------------------------------------------------
__global__ void k_cache(float* __restrict__ out)
{
    const int e = blockIdx.x * 256 + threadIdx.x;
    if (e >= B_SZ * D_CH * CS) return;
    const int i   = e % CS;
    const int bd_ = e / CS;
    const int d   = bd_ & (D_CH - 1);
    const int b   = bd_ >> 9;
    const int tg  = T_TOT - CS + i;
    out[CACHE_OUT_OFF + e] = g_glu[((size_t)tg * B_SZ + b) * D_CH + d];
}

// ---------------------------------------------------------------------------
extern "C" void kernel_launch(void* const* d_in, const int* in_sizes, int n_in,
                              void* d_out, int out_size)
{
    const float* utt   = (const float*)d_in[0];
    const float* rc    = (const float*)d_in[1];
    const float* cache = (const float*)d_in[2];
    const float* w1    = (const float*)d_in[3];
    const float* b1    = (const float*)d_in[4];
    const float* wd    = (const float*)d_in[5];
    const float* bd    = (const float*)d_in[6];
    const float* w2    = (const float*)d_in[7];
    const float* b2    = (const float*)d_in[8];
    float* out = (float*)d_out;

    cudaFuncSetAttribute(k_gemm<0>, cudaFuncAttributeMaxDynamicSharedMemorySize, SMEM_BYTES_H);
    cudaFuncSetAttribute(k_gemm<1>, cudaFuncAttributeMaxDynamicSharedMemorySize, SMEM_BYTES_H);

    // 0) convert operands to fp16
    k_round_a<<<(NROWS * 64) / 256, 256>>>(utt, rc);
    k_round_w<<<(65536 + 32768) / 256, 256>>>(w1, w2);

    // 1) pointwise conv1 + GLU -> g_glu
    k_gemm<0><<<dim3(1024 / 128, NROWS / 128), 256, SMEM_BYTES_H>>>(b1, nullptr);

    // 2) depthwise + swish -> g_zh, cache slice
    k_dw_utt<<<dim3(2, U_LEN / TT, B_SZ), 256>>>(cache, wd, bd);
    k_dw_rc <<<dim3(2, NCHUNK, B_SZ), 256>>>(wd, bd);
    k_cache<<<(B_SZ * D_CH * CS + 255) / 256, 256>>>(out);

    // 3) pointwise conv2 + bias -> final outputs
    k_gemm<1><<<dim3(512 / 128, NROWS / 128), 256, SMEM_BYTES_H>>>(b2, out);
}

// round 15
// speedup vs baseline: 4.4833x; 1.0394x over previous
#include <cuda_runtime.h>
#include <cuda_fp16.h>
#include <cstdint>
#include <math.h>

// Problem constants (fixed shapes)
#define U_LEN   2048
#define B_SZ    16
#define D_CH    512
#define R_LEN   512
#define T_TOT   2560
#define NROWS   40960
#define CS      30
#define KS      31
#define CHUNK   32
#define RCL     8
#define NCHUNK  64
#define RB      (R_LEN * B_SZ)      // 8192

#define UTT_OUT_ELEMS ((size_t)U_LEN * B_SZ * D_CH)
#define RC_OUT_ELEMS  ((size_t)R_LEN * B_SZ * D_CH)
#define CACHE_OUT_OFF (UTT_OUT_ELEMS + RC_OUT_ELEMS)

// fp16 GEMM smem geometry: K-chunk = 32 halves = 16 half2 words, padded to 20
#define LDAH 20                       // words (half2) per row -> conflict-free
#define A_WORDS_H (128 * LDAH)        // 2560
#define B_WORDS_H (128 * LDAH)        // 2560
#define STG_WORDS_H (A_WORDS_H + B_WORDS_H)   // 5120
#define STG_BYTES_H (STG_WORDS_H * 4)         // 20480
#define NSTG 4
#define SMEM_BYTES_H (NSTG * STG_BYTES_H)     // 81920

// Scratch (static device arrays)
__device__ __half g_gluh[(size_t)NROWS * D_CH];     // GLU output (fp16; feeds dw + cache)
__device__ __half g_ah [(size_t)NROWS * D_CH];      // fp16 GEMM1 A
__device__ __half g_zh [(size_t)NROWS * D_CH];      // fp16 dw+swish output (GEMM2 A)
__device__ __half g_w1h[(size_t)2 * D_CH * D_CH];   // fp16, a/g-interleaved W1
__device__ __half g_w2h[(size_t)D_CH * D_CH];       // fp16 W2

static __device__ __forceinline__ float sigmoidf_(float x) {
    return 1.0f / (1.0f + __expf(-x));
}
static __device__ __forceinline__ void mma16(float* c, const unsigned* a, const unsigned* b) {
    asm volatile(
        "mma.sync.aligned.m16n8k16.row.col.f32.f16.f16.f32 "
        "{%0,%1,%2,%3},{%4,%5,%6,%7},{%8,%9},{%0,%1,%2,%3};"
        : "+f"(c[0]), "+f"(c[1]), "+f"(c[2]), "+f"(c[3])
        : "r"(a[0]), "r"(a[1]), "r"(a[2]), "r"(a[3]), "r"(b[0]), "r"(b[1]));
}
static __device__ __forceinline__ void cpa16(unsigned dst, const void* src) {
    asm volatile("cp.async.cg.shared.global [%0], [%1], 16;" :: "r"(dst), "l"(src));
}
static __device__ __forceinline__ void cp_commit() {
    asm volatile("cp.async.commit_group;" ::: "memory");
}
static __device__ __forceinline__ void cp_wait2() {
    asm volatile("cp.async.wait_group 2;" ::: "memory");
}

// ---------------------------------------------------------------------------
// Pre-convert: utt/rc -> g_ah (fp16). One thread = 8 elements.
// ---------------------------------------------------------------------------
__global__ __launch_bounds__(256) void k_round_a(
    const float* __restrict__ utt, const float* __restrict__ rc)
{
    const int idx = blockIdx.x * 256 + threadIdx.x;      // 8-elem group
    const int n = idx >> 6, q = idx & 63;
    const float* src = ((n < RB) ? (rc + (size_t)n * D_CH)
                                 : (utt + (size_t)(n - RB) * D_CH)) + q * 8;
    float4 v0 = *(const float4*)src;
    float4 v1 = *(const float4*)(src + 4);
    __half2 h[4];
    h[0] = __floats2half2_rn(v0.x, v0.y);
    h[1] = __floats2half2_rn(v0.z, v0.w);
    h[2] = __floats2half2_rn(v1.x, v1.y);
    h[3] = __floats2half2_rn(v1.z, v1.w);
    *(uint4*)&g_ah[(size_t)n * D_CH + q * 8] = *(uint4*)h;
}

// w1 (a/g interleaved) -> g_w1h ; w2 -> g_w2h
__global__ __launch_bounds__(256) void k_round_w(
    const float* __restrict__ w1, const float* __restrict__ w2)
{
    const int idx = blockIdx.x * 256 + threadIdx.x;
    const float* src;
    __half* dst;
    if (idx < 65536) {        // g_w1h: 1024 rows; even J='a' row J/2, odd J='g' row 512+J/2
        const int J = idx >> 6, q = idx & 63;
        const int sr = (J & 1) ? (D_CH + (J >> 1)) : (J >> 1);
        src = w1 + (size_t)sr * D_CH + q * 8;
        dst = g_w1h + (size_t)J * D_CH + q * 8;
    } else {
        const int i2 = idx - 65536;
        if (i2 >= 32768) return;
        const int r = i2 >> 6, q = i2 & 63;
        src = w2 + (size_t)r * D_CH + q * 8;
        dst = g_w2h + (size_t)r * D_CH + q * 8;
    }
    float4 v0 = *(const float4*)src;
    float4 v1 = *(const float4*)(src + 4);
    __half2 h[4];
    h[0] = __floats2half2_rn(v0.x, v0.y);
    h[1] = __floats2half2_rn(v0.z, v0.w);
    h[2] = __floats2half2_rn(v1.x, v1.y);
    h[3] = __floats2half2_rn(v1.z, v1.w);
    *(uint4*)dst = *(uint4*)h;
}

// ---------------------------------------------------------------------------
// fp16 tensor-core GEMM: CTA tile M=128 rows x 128 B-rows, K=512 in 16
// chunks of 32, 4-stage cp.async pipeline. 8 warps as 2m x 4n; warp tile
// 64x32 via mma.m16n8k16 (mi=4, nf=4), fp32 accumulate. 2 CTAs/SM.
// MODE 0: GLU-fused conv1 (B = g_w1h interleaved a/g), writes g_gluh (fp16).
// MODE 1: conv2 + bias (B = g_w2h), routed into output regions (fp32).
// ---------------------------------------------------------------------------
template<int MODE>
__global__ __launch_bounds__(256, 2) void k_gemm(
    const float* __restrict__ bias, float* __restrict__ out)
{
    extern __shared__ unsigned smem_u[];

    const int tid  = threadIdx.x;
    const int lane = tid & 31, warp = tid >> 5;
    const int wm   = warp >> 2;      // 0..1
    const int wn   = warp & 3;       // 0..3
    const int row0 = blockIdx.y * 128;
    const int c0   = blockIdx.x * (MODE == 0 ? 64 : 128);

    // Staging: 16B unit = 8 halves; thread -> row (tid>>2)+i*64, quarter tid&3.
    const int tr = tid >> 2, tq = tid & 3;
    const __half* aBase = (MODE == 0 ? g_ah : g_zh)
                        + (size_t)(row0 + tr) * D_CH + tq * 8;
    const __half* bBase = (MODE == 0 ? (g_w1h + (size_t)(2 * c0) * D_CH)
                                     : (g_w2h + (size_t)c0 * D_CH))
                        + (size_t)tr * D_CH + tq * 8;
    const unsigned sbase = (unsigned)__cvta_generic_to_shared(smem_u);
    const unsigned dA = sbase + (unsigned)(tr * LDAH + tq * 4) * 4;
    const unsigned dB = dA + A_WORDS_H * 4;

    // prologue: stages 0..2
    #pragma unroll
    for (int s = 0; s < 3; s++) {
        const unsigned so = (unsigned)(s * STG_BYTES_H);
        #pragma unroll
        for (int i = 0; i < 2; i++)
            cpa16(dA + so + i * (64 * LDAH * 4), aBase + s * 32 + i * (64 * D_CH));
        #pragma unroll
        for (int i = 0; i < 2; i++)
            cpa16(dB + so + i * (64 * LDAH * 4), bBase + s * 32 + i * (64 * D_CH));
        cp_commit();
    }

    float acc[4][4][4];
    #pragma unroll
    for (int mi = 0; mi < 4; mi++)
        #pragma unroll
        for (int f = 0; f < 4; f++)
            #pragma unroll
            for (int q = 0; q < 4; q++) acc[mi][f][q] = 0.f;

    for (int kt = 0; kt < 16; kt++) {
        cp_wait2();
        __syncthreads();

        if (kt + 3 < 16) {
            const int s = kt + 3;
            const unsigned so = (unsigned)((s % NSTG) * STG_BYTES_H);
            #pragma unroll
            for (int i = 0; i < 2; i++)
                cpa16(dA + so + i * (64 * LDAH * 4), aBase + s * 32 + i * (64 * D_CH));
            #pragma unroll
            for (int i = 0; i < 2; i++)
                cpa16(dB + so + i * (64 * LDAH * 4), bBase + s * 32 + i * (64 * D_CH));
        }
        cp_commit();

        const unsigned* A = smem_u + (kt % NSTG) * STG_WORDS_H;
        const unsigned* B = A + A_WORDS_H;

        #pragma unroll
        for (int ks = 0; ks < 2; ks++) {            // two k16 steps per chunk
            const int w0 = ks * 8 + (lane & 3);
            unsigned a[4][4];
            #pragma unroll
            for (int mi = 0; mi < 4; mi++) {
                const int base = (wm * 64 + mi * 16 + (lane >> 2)) * LDAH + w0;
                a[mi][0] = A[base];
                a[mi][1] = A[base + 8 * LDAH];
                a[mi][2] = A[base + 4];
                a[mi][3] = A[base + 8 * LDAH + 4];
            }
            unsigned bf[4][2];
            #pragma unroll
            for (int f = 0; f < 4; f++) {
                const int jn = wn * 32 + f * 8 + (lane >> 2);
                bf[f][0] = B[jn * LDAH + w0];
                bf[f][1] = B[jn * LDAH + w0 + 4];
            }
            #pragma unroll
            for (int mi = 0; mi < 4; mi++)
                #pragma unroll
                for (int f = 0; f < 4; f++)
                    mma16(acc[mi][f], a[mi], bf[f]);
        }
    }

    // Epilogue
    if (MODE == 0) {
        // B-row j = wn*32 + f*8 + 2*(lane&3) + e ; d = c0 + j/2 ; e=0 -> a, e=1 -> g
        #pragma unroll
        for (int f = 0; f < 4; f++) {
            const int d = c0 + wn * 16 + f * 4 + (lane & 3);
            const float ba = bias[d];
            const float bg = bias[D_CH + d];
            #pragma unroll
            for (int mi = 0; mi < 4; mi++) {
                #pragma unroll
                for (int rh = 0; rh < 2; rh++) {
                    const int row = row0 + wm * 64 + mi * 16 + (lane >> 2) + rh * 8;
                    const float a = acc[mi][f][rh * 2 + 0] + ba;
                    const float g = acc[mi][f][rh * 2 + 1] + bg;
                    g_gluh[(size_t)row * D_CH + d] = __float2half_rn(a * sigmoidf_(g));
                }
            }
        }
    } else {
        #pragma unroll
        for (int f = 0; f < 4; f++) {
            const int o = c0 + wn * 32 + f * 8 + 2 * (lane & 3);
            const float b0 = bias[o], b1v = bias[o + 1];
            #pragma unroll
            for (int mi = 0; mi < 4; mi++) {
                #pragma unroll
                for (int rh = 0; rh < 2; rh++) {
                    const int n = row0 + wm * 64 + mi * 16 + (lane >> 2) + rh * 8;
                    float* dst = (n >= RB) ? (out + (size_t)(n - RB) * D_CH)
                                           : (out + UTT_OUT_ELEMS + (size_t)n * D_CH);
                    float2 v;
                    v.x = acc[mi][f][rh * 2 + 0] + b0;
                    v.y = acc[mi][f][rh * 2 + 1] + b1v;
                    *(float2*)&dst[o] = v;
                }
            }
        }
    }
}

// ---------------------------------------------------------------------------
// Depthwise conv (utterance) + swish -> g_zh rows t>=512.
// Sliding 30-reg history window, 32 outputs/thread, outputs in groups of 4
// with batched cur[] prefetch (MLP=4). 4-way split accumulators.
// ---------------------------------------------------------------------------
#define TT 32
__global__ __launch_bounds__(256, 3) void k_dw_utt(
    const float* __restrict__ cache,
    const float* __restrict__ wd, const float* __restrict__ bd)
{
    const int d  = blockIdx.x * 256 + threadIdx.x;
    const int t0 = blockIdx.y * TT;
    const int b  = blockIdx.z;

    float w[KS];
    #pragma unroll
    for (int k = 0; k < KS; k++) w[k] = wd[(size_t)d * KS + k];

    float h[CS];   // pad[t0 .. t0+29]
    #pragma unroll
    for (int p = 0; p < CS; p++) {
        const int pp = t0 + p;
        if (pp < CS)
            h[p] = cache[((size_t)b * D_CH + d) * CS + pp];
        else
            h[p] = __half2float(g_gluh[((size_t)(R_LEN + pp - CS) * B_SZ + b) * D_CH + d]);
    }

    const float bias = bd[d];
    #pragma unroll
    for (int jo = 0; jo < TT; jo += 4) {
        float cur[4];
        #pragma unroll
        for (int u = 0; u < 4; u++)
            cur[u] = __half2float(
                g_gluh[((size_t)(R_LEN + t0 + jo + u) * B_SZ + b) * D_CH + d]);
        #pragma unroll
        for (int u = 0; u < 4; u++) {
            float s0 = bias, s1 = 0.f, s2 = 0.f, s3 = 0.f;
            #pragma unroll
            for (int k = 0; k < 28; k += 4) {
                s0 += w[k + 0] * h[k + 0];
                s1 += w[k + 1] * h[k + 1];
                s2 += w[k + 2] * h[k + 2];
                s3 += w[k + 3] * h[k + 3];
            }
            s0 += w[28] * h[28];
            s1 += w[29] * h[29];
            s2 += w[30] * cur[u];
            const float acc = (s0 + s1) + (s2 + s3);
            const float r = acc * sigmoidf_(acc - 1.0f);
            g_zh[((size_t)(R_LEN + t0 + jo + u) * B_SZ + b) * D_CH + d] =
                __float2half_rn(r);
            #pragma unroll
            for (int k = 0; k < CS - 1; k++) h[k] = h[k + 1];
            h[CS - 1] = cur[u];
        }
    }
}

// ---------------------------------------------------------------------------
// Depthwise conv (right-context chunks) + swish -> g_zh rows t<512.
// ---------------------------------------------------------------------------
__global__ __launch_bounds__(256) void k_dw_rc(
    const float* __restrict__ wd, const float* __restrict__ bd)
{
    const int d = blockIdx.x * 256 + threadIdx.x;
    const int c = blockIdx.y;
    const int b = blockIdx.z;

    float w[KS];
    #pragma unroll
    for (int k = 0; k < KS; k++) w[k] = wd[(size_t)d * KS + k];

    float s[38];
    const int base_t = R_LEN + (c + 1) * CHUNK - CS;
    #pragma unroll
    for (int p = 0; p < 30; p++)
        s[p] = __half2float(g_gluh[((size_t)(base_t + p) * B_SZ + b) * D_CH + d]);
    #pragma unroll
    for (int p = 0; p < 8; p++)
        s[30 + p] = __half2float(g_gluh[((size_t)(c * RCL + p) * B_SZ + b) * D_CH + d]);

    const float bias = bd[d];
    #pragma unroll
    for (int j = 0; j < RCL; j++) {
        float s0 = bias, s1 = 0.f, s2 = 0.f, s3 = 0.f;
        #pragma unroll
        for (int k = 0; k < 28; k += 4) {
            s0 += w[k + 0] * s[j + k + 0];
            s1 += w[k + 1] * s[j + k + 1];
            s2 += w[k + 2] * s[j + k + 2];
            s3 += w[k + 3] * s[j + k + 3];
        }
        s0 += w[28] * s[j + 28];
        s1 += w[29] * s[j + 29];
        s2 += w[30] * s[j + 30];
        const float acc = (s0 + s1) + (s2 + s3);
        const float r = acc * sigmoidf_(acc - 1.0f);
        const int tg = c * RCL + j;
        g_zh[((size_t)tg * B_SZ + b) * D_CH + d] = __float2half_rn(r);
    }
}

// ---------------------------------------------------------------------------
// new_cache slice (from fp16 GLU)
// ---------------------------------------------------------------------------
__global__ void k_cache(float* __restrict__ out)
{
    const int e = blockIdx.x * 256 + threadIdx.x;
    if (e >= B_SZ * D_CH * CS) return;
    const int i   = e % CS;
    const int bd_ = e / CS;
    const int d   = bd_ & (D_CH - 1);
    const int b   = bd_ >> 9;
    const int tg  = T_TOT - CS + i;
    out[CACHE_OUT_OFF + e] =
        __half2float(g_gluh[((size_t)tg * B_SZ + b) * D_CH + d]);
}

// ---------------------------------------------------------------------------
extern "C" void kernel_launch(void* const* d_in, const int* in_sizes, int n_in,
                              void* d_out, int out_size)
{
    const float* utt   = (const float*)d_in[0];
    const float* rc    = (const float*)d_in[1];
    const float* cache = (const float*)d_in[2];
    const float* w1    = (const float*)d_in[3];
    const float* b1    = (const float*)d_in[4];
    const float* wd    = (const float*)d_in[5];
    const float* bd    = (const float*)d_in[6];
    const float* w2    = (const float*)d_in[7];
    const float* b2    = (const float*)d_in[8];
    float* out = (float*)d_out;

    cudaFuncSetAttribute(k_gemm<0>, cudaFuncAttributeMaxDynamicSharedMemorySize, SMEM_BYTES_H);
    cudaFuncSetAttribute(k_gemm<1>, cudaFuncAttributeMaxDynamicSharedMemorySize, SMEM_BYTES_H);

    // 0) convert operands to fp16
    k_round_a<<<(NROWS * 64) / 256, 256>>>(utt, rc);
    k_round_w<<<(65536 + 32768) / 256, 256>>>(w1, w2);

    // 1) pointwise conv1 + GLU -> g_gluh
    k_gemm<0><<<dim3(1024 / 128, NROWS / 128), 256, SMEM_BYTES_H>>>(b1, nullptr);

    // 2) depthwise + swish -> g_zh, cache slice
    k_dw_utt<<<dim3(2, U_LEN / TT, B_SZ), 256>>>(cache, wd, bd);
    k_dw_rc <<<dim3(2, NCHUNK, B_SZ), 256>>>(wd, bd);
    k_cache<<<(B_SZ * D_CH * CS + 255) / 256, 256>>>(out);

    // 3) pointwise conv2 + bias -> final outputs
    k_gemm<1><<<dim3(512 / 128, NROWS / 128), 256, SMEM_BYTES_H>>>(b2, out);
}

// round 16
// speedup vs baseline: 4.7479x; 1.0590x over previous
#include <cuda_runtime.h>
#include <cuda_fp16.h>
#include <cstdint>
#include <math.h>

// Problem constants (fixed shapes)
#define U_LEN   2048
#define B_SZ    16
#define D_CH    512
#define R_LEN   512
#define T_TOT   2560
#define NROWS   40960
#define CS      30
#define KS      31
#define CHUNK   32
#define RCL     8
#define NCHUNK  64
#define RB      (R_LEN * B_SZ)      // 8192
#define TB_STRIDE 8192              // B_SZ * D_CH, elements between consecutive t

#define UTT_OUT_ELEMS ((size_t)U_LEN * B_SZ * D_CH)
#define RC_OUT_ELEMS  ((size_t)R_LEN * B_SZ * D_CH)
#define CACHE_OUT_OFF (UTT_OUT_ELEMS + RC_OUT_ELEMS)

// fp16 GEMM smem geometry: K-chunk = 32 halves = 16 half2 words, padded to 20
#define LDAH 20                       // words (half2) per row -> conflict-free
#define A_WORDS_H (128 * LDAH)        // 2560
#define B_WORDS_H (128 * LDAH)        // 2560
#define STG_WORDS_H (A_WORDS_H + B_WORDS_H)   // 5120
#define STG_BYTES_H (STG_WORDS_H * 4)         // 20480
#define NSTG 4
#define SMEM_BYTES_H (NSTG * STG_BYTES_H)     // 81920

// Scratch (static device arrays)
__device__ __half g_gluh[(size_t)NROWS * D_CH];     // GLU output (fp16; feeds dw + cache)
__device__ __half g_ah [(size_t)NROWS * D_CH];      // fp16 GEMM1 A
__device__ __half g_zh [(size_t)NROWS * D_CH];      // fp16 dw+swish output (GEMM2 A)
__device__ __half g_w1h[(size_t)2 * D_CH * D_CH];   // fp16, a/g-interleaved W1
__device__ __half g_w2h[(size_t)D_CH * D_CH];       // fp16 W2

static __device__ __forceinline__ float sigmoidf_(float x) {
    return 1.0f / (1.0f + __expf(-x));
}
static __device__ __forceinline__ void mma16(float* c, const unsigned* a, const unsigned* b) {
    asm volatile(
        "mma.sync.aligned.m16n8k16.row.col.f32.f16.f16.f32 "
        "{%0,%1,%2,%3},{%4,%5,%6,%7},{%8,%9},{%0,%1,%2,%3};"
        : "+f"(c[0]), "+f"(c[1]), "+f"(c[2]), "+f"(c[3])
        : "r"(a[0]), "r"(a[1]), "r"(a[2]), "r"(a[3]), "r"(b[0]), "r"(b[1]));
}
static __device__ __forceinline__ void cpa16(unsigned dst, const void* src) {
    asm volatile("cp.async.cg.shared.global [%0], [%1], 16;" :: "r"(dst), "l"(src));
}
static __device__ __forceinline__ void cp_commit() {
    asm volatile("cp.async.commit_group;" ::: "memory");
}
static __device__ __forceinline__ void cp_wait2() {
    asm volatile("cp.async.wait_group 2;" ::: "memory");
}

// ---------------------------------------------------------------------------
// Merged pre-convert: utt/rc -> g_ah ; w1 (a/g interleaved) -> g_w1h ; w2 -> g_w2h
// One thread = 8 elements (fp32 read -> fp16 write).
// ---------------------------------------------------------------------------
#define PRE_A_GROUPS (NROWS * 64)          // 2621440
__global__ __launch_bounds__(256) void k_pre(
    const float* __restrict__ utt, const float* __restrict__ rc,
    const float* __restrict__ w1, const float* __restrict__ w2)
{
    int idx = blockIdx.x * 256 + threadIdx.x;
    const float* src;
    __half* dst;
    if (idx < PRE_A_GROUPS) {
        const int n = idx >> 6, q = idx & 63;
        src = ((n < RB) ? (rc + (size_t)n * D_CH)
                        : (utt + (size_t)(n - RB) * D_CH)) + q * 8;
        dst = g_ah + (size_t)n * D_CH + q * 8;
    } else {
        idx -= PRE_A_GROUPS;
        if (idx < 65536) {    // g_w1h: even J='a' row J/2, odd J='g' row 512+J/2
            const int J = idx >> 6, q = idx & 63;
            const int sr = (J & 1) ? (D_CH + (J >> 1)) : (J >> 1);
            src = w1 + (size_t)sr * D_CH + q * 8;
            dst = g_w1h + (size_t)J * D_CH + q * 8;
        } else {
            idx -= 65536;
            if (idx >= 32768) return;
            const int r = idx >> 6, q = idx & 63;
            src = w2 + (size_t)r * D_CH + q * 8;
            dst = g_w2h + (size_t)r * D_CH + q * 8;
        }
    }
    float4 v0 = *(const float4*)src;
    float4 v1 = *(const float4*)(src + 4);
    __half2 h[4];
    h[0] = __floats2half2_rn(v0.x, v0.y);
    h[1] = __floats2half2_rn(v0.z, v0.w);
    h[2] = __floats2half2_rn(v1.x, v1.y);
    h[3] = __floats2half2_rn(v1.z, v1.w);
    *(uint4*)dst = *(uint4*)h;
}

// ---------------------------------------------------------------------------
// fp16 tensor-core GEMM: CTA tile M=128 rows x 128 B-rows, K=512 in 16
// chunks of 32, 4-stage cp.async pipeline. 8 warps as 2m x 4n; warp tile
// 64x32 via mma.m16n8k16 (mi=4, nf=4), fp32 accumulate. 2 CTAs/SM.
// MODE 0: GLU-fused conv1 (B = g_w1h interleaved a/g), writes g_gluh (fp16).
// MODE 1: conv2 + bias (B = g_w2h), routed into output regions (fp32).
// ---------------------------------------------------------------------------
template<int MODE>
__global__ __launch_bounds__(256, 2) void k_gemm(
    const float* __restrict__ bias, float* __restrict__ out)
{
    extern __shared__ unsigned smem_u[];

    const int tid  = threadIdx.x;
    const int lane = tid & 31, warp = tid >> 5;
    const int wm   = warp >> 2;      // 0..1
    const int wn   = warp & 3;       // 0..3
    const int row0 = blockIdx.y * 128;
    const int c0   = blockIdx.x * (MODE == 0 ? 64 : 128);

    // Staging: 16B unit = 8 halves; thread -> row (tid>>2)+i*64, quarter tid&3.
    const int tr = tid >> 2, tq = tid & 3;
    const __half* aBase = (MODE == 0 ? g_ah : g_zh)
                        + (size_t)(row0 + tr) * D_CH + tq * 8;
    const __half* bBase = (MODE == 0 ? (g_w1h + (size_t)(2 * c0) * D_CH)
                                     : (g_w2h + (size_t)c0 * D_CH))
                        + (size_t)tr * D_CH + tq * 8;
    const unsigned sbase = (unsigned)__cvta_generic_to_shared(smem_u);
    const unsigned dA = sbase + (unsigned)(tr * LDAH + tq * 4) * 4;
    const unsigned dB = dA + A_WORDS_H * 4;

    // prologue: stages 0..2
    #pragma unroll
    for (int s = 0; s < 3; s++) {
        const unsigned so = (unsigned)(s * STG_BYTES_H);
        #pragma unroll
        for (int i = 0; i < 2; i++)
            cpa16(dA + so + i * (64 * LDAH * 4), aBase + s * 32 + i * (64 * D_CH));
        #pragma unroll
        for (int i = 0; i < 2; i++)
            cpa16(dB + so + i * (64 * LDAH * 4), bBase + s * 32 + i * (64 * D_CH));
        cp_commit();
    }

    float acc[4][4][4];
    #pragma unroll
    for (int mi = 0; mi < 4; mi++)
        #pragma unroll
        for (int f = 0; f < 4; f++)
            #pragma unroll
            for (int q = 0; q < 4; q++) acc[mi][f][q] = 0.f;

    for (int kt = 0; kt < 16; kt++) {
        cp_wait2();
        __syncthreads();

        if (kt + 3 < 16) {
            const int s = kt + 3;
            const unsigned so = (unsigned)((s % NSTG) * STG_BYTES_H);
            #pragma unroll
            for (int i = 0; i < 2; i++)
                cpa16(dA + so + i * (64 * LDAH * 4), aBase + s * 32 + i * (64 * D_CH));
            #pragma unroll
            for (int i = 0; i < 2; i++)
                cpa16(dB + so + i * (64 * LDAH * 4), bBase + s * 32 + i * (64 * D_CH));
        }
        cp_commit();

        const unsigned* A = smem_u + (kt % NSTG) * STG_WORDS_H;
        const unsigned* B = A + A_WORDS_H;

        #pragma unroll
        for (int ks = 0; ks < 2; ks++) {            // two k16 steps per chunk
            const int w0 = ks * 8 + (lane & 3);
            unsigned a[4][4];
            #pragma unroll
            for (int mi = 0; mi < 4; mi++) {
                const int base = (wm * 64 + mi * 16 + (lane >> 2)) * LDAH + w0;
                a[mi][0] = A[base];
                a[mi][1] = A[base + 8 * LDAH];
                a[mi][2] = A[base + 4];
                a[mi][3] = A[base + 8 * LDAH + 4];
            }
            unsigned bf[4][2];
            #pragma unroll
            for (int f = 0; f < 4; f++) {
                const int jn = wn * 32 + f * 8 + (lane >> 2);
                bf[f][0] = B[jn * LDAH + w0];
                bf[f][1] = B[jn * LDAH + w0 + 4];
            }
            #pragma unroll
            for (int mi = 0; mi < 4; mi++)
                #pragma unroll
                for (int f = 0; f < 4; f++)
                    mma16(acc[mi][f], a[mi], bf[f]);
        }
    }

    // Epilogue
    if (MODE == 0) {
        // B-row j = wn*32 + f*8 + 2*(lane&3) + e ; d = c0 + j/2 ; e=0 -> a, e=1 -> g
        #pragma unroll
        for (int f = 0; f < 4; f++) {
            const int d = c0 + wn * 16 + f * 4 + (lane & 3);
            const float ba = bias[d];
            const float bg = bias[D_CH + d];
            #pragma unroll
            for (int mi = 0; mi < 4; mi++) {
                #pragma unroll
                for (int rh = 0; rh < 2; rh++) {
                    const int row = row0 + wm * 64 + mi * 16 + (lane >> 2) + rh * 8;
                    const float a = acc[mi][f][rh * 2 + 0] + ba;
                    const float g = acc[mi][f][rh * 2 + 1] + bg;
                    g_gluh[(size_t)row * D_CH + d] = __float2half_rn(a * sigmoidf_(g));
                }
            }
        }
    } else {
        #pragma unroll
        for (int f = 0; f < 4; f++) {
            const int o = c0 + wn * 32 + f * 8 + 2 * (lane & 3);
            const float b0 = bias[o], b1v = bias[o + 1];
            #pragma unroll
            for (int mi = 0; mi < 4; mi++) {
                #pragma unroll
                for (int rh = 0; rh < 2; rh++) {
                    const int n = row0 + wm * 64 + mi * 16 + (lane >> 2) + rh * 8;
                    float* dst = (n >= RB) ? (out + (size_t)(n - RB) * D_CH)
                                           : (out + UTT_OUT_ELEMS + (size_t)n * D_CH);
                    float2 v;
                    v.x = acc[mi][f][rh * 2 + 0] + b0;
                    v.y = acc[mi][f][rh * 2 + 1] + b1v;
                    *(float2*)&dst[o] = v;
                }
            }
        }
    }
}

// ---------------------------------------------------------------------------
// Merged middle kernel. All three regions depend only on g_gluh (and inputs):
//   y in [0,64)    : depthwise conv utterance + swish -> g_zh rows t>=512
//   y in [64,128)  : depthwise conv rc chunks + swish -> g_zh rows t<512
//   y in [128,158) : new_cache slice -> out
// Grid dim3(2, 158, 16). Small regions fill dw_utt occupancy gaps.
// ---------------------------------------------------------------------------
#define TT 32
__global__ __launch_bounds__(256, 3) void k_mid(
    const float* __restrict__ cache,
    const float* __restrict__ wd, const float* __restrict__ bd,
    float* __restrict__ out)
{
    const int y = blockIdx.y;

    if (y < 64) {
        // ---- depthwise utterance ----
        const int d  = blockIdx.x * 256 + threadIdx.x;
        const int t0 = y * TT;
        const int b  = blockIdx.z;

        float w[KS];
        #pragma unroll
        for (int k = 0; k < KS; k++) w[k] = wd[d * KS + k];

        const int idx0 = ((R_LEN + t0) * B_SZ + b) * D_CH + d;  // first 'cur'

        float h[CS];   // pad[t0 .. t0+29]
        if (t0 == 0) {
            const float* cp_ = cache + ((size_t)b * D_CH + d) * CS;
            #pragma unroll
            for (int p = 0; p < CS; p++) h[p] = cp_[p];
        } else {
            const __half* hp = g_gluh + (idx0 - CS * TB_STRIDE);
            #pragma unroll
            for (int p = 0; p < CS; p++) h[p] = __half2float(hp[p * TB_STRIDE]);
        }

        const float bias = bd[d];
        const __half* cp = g_gluh + idx0;
        __half*       zp = g_zh  + idx0;
        #pragma unroll
        for (int jo = 0; jo < TT; jo += 4) {
            float cur[4];
            #pragma unroll
            for (int u = 0; u < 4; u++)
                cur[u] = __half2float(cp[u * TB_STRIDE]);
            #pragma unroll
            for (int u = 0; u < 4; u++) {
                float s0 = bias, s1 = 0.f, s2 = 0.f, s3 = 0.f;
                #pragma unroll
                for (int k = 0; k < 28; k += 4) {
                    s0 += w[k + 0] * h[k + 0];
                    s1 += w[k + 1] * h[k + 1];
                    s2 += w[k + 2] * h[k + 2];
                    s3 += w[k + 3] * h[k + 3];
                }
                s0 += w[28] * h[28];
                s1 += w[29] * h[29];
                s2 += w[30] * cur[u];
                const float acc = (s0 + s1) + (s2 + s3);
                const float r = acc * sigmoidf_(acc - 1.0f);
                zp[u * TB_STRIDE] = __float2half_rn(r);
                #pragma unroll
                for (int k = 0; k < CS - 1; k++) h[k] = h[k + 1];
                h[CS - 1] = cur[u];
            }
            cp += 4 * TB_STRIDE;
            zp += 4 * TB_STRIDE;
        }
    } else if (y < 128) {
        // ---- depthwise right-context chunks ----
        const int d = blockIdx.x * 256 + threadIdx.x;
        const int c = y - 64;
        const int b = blockIdx.z;

        float w[KS];
        #pragma unroll
        for (int k = 0; k < KS; k++) w[k] = wd[d * KS + k];

        float s[38];
        const int base_t = R_LEN + (c + 1) * CHUNK - CS;
        const __half* hp = g_gluh + (base_t * B_SZ + b) * D_CH + d;
        #pragma unroll
        for (int p = 0; p < 30; p++)
            s[p] = __half2float(hp[p * TB_STRIDE]);
        const __half* rp = g_gluh + ((c * RCL) * B_SZ + b) * D_CH + d;
        #pragma unroll
        for (int p = 0; p < 8; p++)
            s[30 + p] = __half2float(rp[p * TB_STRIDE]);

        const float bias = bd[d];
        __half* zp = g_zh + ((c * RCL) * B_SZ + b) * D_CH + d;
        #pragma unroll
        for (int j = 0; j < RCL; j++) {
            float s0 = bias, s1 = 0.f, s2 = 0.f, s3 = 0.f;
            #pragma unroll
            for (int k = 0; k < 28; k += 4) {
                s0 += w[k + 0] * s[j + k + 0];
                s1 += w[k + 1] * s[j + k + 1];
                s2 += w[k + 2] * s[j + k + 2];
                s3 += w[k + 3] * s[j + k + 3];
            }
            s0 += w[28] * s[j + 28];
            s1 += w[29] * s[j + 29];
            s2 += w[30] * s[j + 30];
            const float acc = (s0 + s1) + (s2 + s3);
            const float r = acc * sigmoidf_(acc - 1.0f);
            zp[j * TB_STRIDE] = __float2half_rn(r);
        }
    } else {
        // ---- new_cache slice ----
        const int cb = (y - 128) + 30 * (blockIdx.x + 2 * blockIdx.z);  // 0..959
        const int e  = cb * 256 + threadIdx.x;
        const int i   = e % CS;
        const int bd_ = e / CS;
        const int d   = bd_ & (D_CH - 1);
        const int b   = bd_ >> 9;
        const int tg  = T_TOT - CS + i;
        out[CACHE_OUT_OFF + e] =
            __half2float(g_gluh[((size_t)tg * B_SZ + b) * D_CH + d]);
    }
}

// ---------------------------------------------------------------------------
extern "C" void kernel_launch(void* const* d_in, const int* in_sizes, int n_in,
                              void* d_out, int out_size)
{
    const float* utt   = (const float*)d_in[0];
    const float* rc    = (const float*)d_in[1];
    const float* cache = (const float*)d_in[2];
    const float* w1    = (const float*)d_in[3];
    const float* b1    = (const float*)d_in[4];
    const float* wd    = (const float*)d_in[5];
    const float* bd    = (const float*)d_in[6];
    const float* w2    = (const float*)d_in[7];
    const float* b2    = (const float*)d_in[8];
    float* out = (float*)d_out;

    cudaFuncSetAttribute(k_gemm<0>, cudaFuncAttributeMaxDynamicSharedMemorySize, SMEM_BYTES_H);
    cudaFuncSetAttribute(k_gemm<1>, cudaFuncAttributeMaxDynamicSharedMemorySize, SMEM_BYTES_H);

    // 0) convert operands to fp16 (merged)
    k_pre<<<(PRE_A_GROUPS + 65536 + 32768) / 256, 256>>>(utt, rc, w1, w2);

    // 1) pointwise conv1 + GLU -> g_gluh
    k_gemm<0><<<dim3(1024 / 128, NROWS / 128), 256, SMEM_BYTES_H>>>(b1, nullptr);

    // 2) depthwise + swish -> g_zh, cache slice (merged)
    k_mid<<<dim3(2, 158, B_SZ), 256>>>(cache, wd, bd, out);

    // 3) pointwise conv2 + bias -> final outputs
    k_gemm<1><<<dim3(512 / 128, NROWS / 128), 256, SMEM_BYTES_H>>>(b2, out);
}